// round 8
// baseline (speedup 1.0000x reference)
#include <cuda_runtime.h>
#include <cuda_bf16.h>
#include <cstdint>

// ---------------------------------------------------------------------------
// Problem constants
// ---------------------------------------------------------------------------
#define N_TOK   65536
#define C_CODES 2048
#define D       64
#define KEXT    208                  // [ah|ah|al|1,1,0..] x [eh|el|eh|e2h,e2l,0..]
#define M_TILE  256
#define N_TILE  128                  // codes per chunk
#define NCHUNK  (C_CODES / N_TILE)   // 16
#define KSTEPS  (KEXT / 16)          // 13
#define MARGIN  0.02f
#define NTHR    512

#define DECAY_F 0.8f
#define OMD_F   0.2f
#define EPS_F   1e-5f

// smem row stride 432 B (108 words ≡ 12 mod 32 -> ldmatrix conflict-free)
#define RSTRIDE      432
#define A_BYTES      (M_TILE * RSTRIDE)      // 110592
#define BCH_BYTES    (N_TILE * RSTRIDE)      // 55296
#define SMEM_B_OFF   A_BYTES
#define SMEM_DYN     (A_BYTES + 2 * BCH_BYTES)   // 221184 (<= 227KB cap)

// k_exact smem
#define EX_RS        68
#define EX_SMEM      (256*EX_RS*4 + 32*64*4 + 256*4 + 128)  // 78976

// Output layout (floats), reference return order
#define OFF_Q    0
#define OFF_IND  4194304
#define OFF_NE   4259840
#define OFF_NCS  4390912
#define OFF_NEA  4392960

// ---------------------------------------------------------------------------
// Device scratch
// ---------------------------------------------------------------------------
__device__ __nv_bfloat16 g_B[(size_t)C_CODES * KEXT];
__device__ float g_e2[C_CODES];
__device__ int   g_ind[N_TOK];
__device__ float g_counts[C_CODES];
__device__ float g_sum[C_CODES * D];
__device__ int   g_namb;
__device__ int   g_amb[N_TOK];
__device__ unsigned long long g_bestpack[N_TOK];

// ---------------------------------------------------------------------------
// PTX helpers (baseline sm_80-era only — safe on plain sm_103 target)
// ---------------------------------------------------------------------------
__device__ __forceinline__ uint32_t smem_u32(const void* p) {
    return (uint32_t)__cvta_generic_to_shared(p);
}
__device__ __forceinline__ void cp16(uint32_t saddr, const void* g) {
    asm volatile("cp.async.cg.shared.global [%0], [%1], 16;" :: "r"(saddr), "l"(g));
}
__device__ __forceinline__ void cp_commit() {
    asm volatile("cp.async.commit_group;" ::: "memory");
}
template <int NN> __device__ __forceinline__ void cp_wait() {
    asm volatile("cp.async.wait_group %0;" :: "n"(NN) : "memory");
}
__device__ __forceinline__ void ldsm4(uint32_t* r, uint32_t addr) {
    asm volatile("ldmatrix.sync.aligned.m8n8.x4.shared.b16 {%0,%1,%2,%3}, [%4];"
                 : "=r"(r[0]), "=r"(r[1]), "=r"(r[2]), "=r"(r[3]) : "r"(addr));
}
__device__ __forceinline__ void mma16816(float* d, const uint32_t* a,
                                         uint32_t b0, uint32_t b1) {
    asm volatile(
        "mma.sync.aligned.m16n8k16.row.col.f32.bf16.bf16.f32 "
        "{%0,%1,%2,%3}, {%4,%5,%6,%7}, {%8,%9}, {%0,%1,%2,%3};"
        : "+f"(d[0]), "+f"(d[1]), "+f"(d[2]), "+f"(d[3])
        : "r"(a[0]), "r"(a[1]), "r"(a[2]), "r"(a[3]), "r"(b0), "r"(b1));
}

// ---------------------------------------------------------------------------
// k_zero
// ---------------------------------------------------------------------------
__global__ void k_zero() {
    int i = blockIdx.x * blockDim.x + threadIdx.x;
    if (i == 0) g_namb = 0;
    if (i < C_CODES) g_counts[i] = 0.0f;
    if (i < C_CODES * D) g_sum[i] = 0.0f;
    if (i < N_TOK) g_bestpack[i] = 0xFFFFFFFFFFFFFFFFull;
}

// ---------------------------------------------------------------------------
// k_prep_b: B row = [eh | el | eh | e2h,e2l, 0...] bf16; e2 fp32 for k_exact.
// ---------------------------------------------------------------------------
__global__ void k_prep_b(const float* __restrict__ emb) {
    int c = (blockIdx.x * blockDim.x + threadIdx.x) >> 5;
    int lane = threadIdx.x & 31;
    if (c >= C_CODES) return;
    float2 v = *(const float2*)(emb + (size_t)c * D + lane * 2);
    __nv_bfloat16 h0 = __float2bfloat16(v.x), h1 = __float2bfloat16(v.y);
    __nv_bfloat16 l0 = __float2bfloat16(v.x - __bfloat162float(h0));
    __nv_bfloat16 l1 = __float2bfloat16(v.y - __bfloat162float(h1));
    float sq = v.x * v.x + v.y * v.y;
    #pragma unroll
    for (int m = 16; m >= 1; m >>= 1)
        sq += __shfl_xor_sync(0xFFFFFFFFu, sq, m);
    __nv_bfloat162 hh; hh.x = h0; hh.y = h1;
    __nv_bfloat162 ll; ll.x = l0; ll.y = l1;
    __nv_bfloat162* base = (__nv_bfloat162*)(g_B + (size_t)c * KEXT);
    base[lane] = hh; base[32 + lane] = ll; base[64 + lane] = hh;
    if (lane == 0) {
        __nv_bfloat16 s2h = __float2bfloat16(sq);
        __nv_bfloat16 s2l = __float2bfloat16(sq - __bfloat162float(s2h));
        __nv_bfloat162 z; z.x = __float2bfloat16(0.f); z.y = z.x;
        __nv_bfloat162 e2p; e2p.x = s2h; e2p.y = s2l;
        base[96] = e2p;
        #pragma unroll
        for (int q = 97; q < 104; q++) base[q] = z;
        g_e2[c] = sq;
    }
}

// ---------------------------------------------------------------------------
// k_mma: HMMA split-GEMM (K=208, e2 folded) + fused argmin, margin detect.
// CTA = 512 thr = 16 warps (4m x 4n). Warp tile mt=4 x nt=4. M=256, N=128.
// ---------------------------------------------------------------------------
__device__ __forceinline__ void issue_b(uint32_t dst, const __nv_bfloat16* src,
                                        int tid) {
    // 128 rows x 26 float4 (416 valid bytes of 432 row)
    #pragma unroll
    for (int it = 0; it < 7; it++) {
        int i = tid + it * NTHR;
        if (i < 128 * 26) {
            int n = i / 26, q = i - n * 26;
            cp16(dst + n * RSTRIDE + q * 16, src + (size_t)n * KEXT + q * 8);
        }
    }
}

extern __shared__ char smraw[];

__global__ __launch_bounds__(NTHR, 1) void k_mma(const float* __restrict__ x) {
    uint32_t A_s = smem_u32(smraw);
    uint32_t B_s = A_s + SMEM_B_OFF;

    int tid = threadIdx.x;
    int lane = tid & 31, wid = tid >> 5;
    int warp_m = wid >> 2, warp_n = wid & 3;
    int g   = lane >> 2;
    int tig = lane & 3;
    int row0 = blockIdx.x * M_TILE;

    // prologue: B chunk 0
    issue_b(B_s, g_B, tid);
    cp_commit();

    // build A tile: [bf16(-2x)|dup|residual|1,1,0...], 256 rows
    {
        const float2* xsrc = (const float2*)(x + (size_t)row0 * D);
        for (int idx = tid; idx < M_TILE * 32; idx += NTHR) {
            int r = idx >> 5, c2 = idx & 31;
            float2 v = xsrc[r * 32 + c2];
            float a0 = -2.0f * v.x, a1 = -2.0f * v.y;
            __nv_bfloat16 h0 = __float2bfloat16(a0), h1 = __float2bfloat16(a1);
            __nv_bfloat16 l0 = __float2bfloat16(a0 - __bfloat162float(h0));
            __nv_bfloat16 l1 = __float2bfloat16(a1 - __bfloat162float(h1));
            __nv_bfloat162 hh; hh.x = h0; hh.y = h1;
            __nv_bfloat162 ll; ll.x = l0; ll.y = l1;
            __nv_bfloat162* rowp = (__nv_bfloat162*)(smraw + r * RSTRIDE);
            rowp[c2] = hh; rowp[32 + c2] = hh; rowp[64 + c2] = ll;
        }
        for (int r = tid; r < M_TILE; r += NTHR) {
            uint4* tailp = (uint4*)(smraw + r * RSTRIDE + 384);
            tailp[0] = make_uint4(0x3F803F80u, 0u, 0u, 0u);
            tailp[1] = make_uint4(0u, 0u, 0u, 0u);
        }
    }

    int lrow = lane & 15, lsel = lane >> 4;
    // A fragment bases: 4 m-tiles of 16 rows at warp_m*64
    uint32_t a_ad[4];
    #pragma unroll
    for (int mt = 0; mt < 4; mt++)
        a_ad[mt] = A_s + (uint32_t)(warp_m * 64 + mt * 16 + lrow) * RSTRIDE
                 + lsel * 16;
    // B fragment bases: 2 ldsm of 16 codes each at warp_n*32
    uint32_t b_off0 = (uint32_t)(warp_n * 32 + lrow) * RSTRIDE + lsel * 16;
    uint32_t b_off1 = b_off0 + 16 * RSTRIDE;

    float best[8], b2[8]; int bidx[8];
    #pragma unroll
    for (int i = 0; i < 8; i++) { best[i] = 3.4e38f; b2[i] = 3.4e38f; bidx[i] = 0; }

    for (int ch = 0; ch < NCHUNK; ch++) {
        cp_wait<0>();
        __syncthreads();
        if (ch + 1 < NCHUNK) {
            issue_b(B_s + ((ch + 1) & 1) * BCH_BYTES,
                    g_B + (size_t)(ch + 1) * N_TILE * KEXT, tid);
            cp_commit();
        }

        uint32_t bb = B_s + (ch & 1) * BCH_BYTES;
        uint32_t pb0 = bb + b_off0, pb1 = bb + b_off1;

        float acc[4][4][4];
        #pragma unroll
        for (int mt = 0; mt < 4; mt++)
            #pragma unroll
            for (int nt = 0; nt < 4; nt++)
                #pragma unroll
                for (int q = 0; q < 4; q++) acc[mt][nt][q] = 0.0f;

        #pragma unroll
        for (int ks = 0; ks < KSTEPS; ks++) {
            uint32_t B0[4], B1[4];
            ldsm4(B0, pb0 + ks * 32);
            ldsm4(B1, pb1 + ks * 32);
            #pragma unroll
            for (int mt = 0; mt < 4; mt++) {
                uint32_t Af[4];
                ldsm4(Af, a_ad[mt] + ks * 32);
                mma16816(acc[mt][0], Af, B0[0], B0[2]);
                mma16816(acc[mt][1], Af, B0[1], B0[3]);
                mma16816(acc[mt][2], Af, B1[0], B1[2]);
                mma16816(acc[mt][3], Af, B1[1], B1[3]);
            }
        }

        // branchless epilogue: pack 3-bit local idx into mantissa LSBs,
        // per-row-stream (m1, m2) via min/max chains, one unpack per chunk.
        #pragma unroll
        for (int mt = 0; mt < 4; mt++)
            #pragma unroll
            for (int e = 0; e < 2; e++) {
                int ri = mt * 2 + e;
                float m1 = 3.4e38f, m2 = 3.4e38f;
                #pragma unroll
                for (int nt = 0; nt < 4; nt++)
                    #pragma unroll
                    for (int b = 0; b < 2; b++) {
                        float s = acc[mt][nt][e * 2 + b];
                        uint32_t u = (__float_as_uint(s) & ~7u) |
                                     (uint32_t)(nt * 2 + b);
                        float sp = __uint_as_float(u);
                        m2 = fminf(m2, fmaxf(m1, sp));
                        m1 = fminf(m1, sp);
                    }
                uint32_t lu = __float_as_uint(m1) & 7u;
                int code = ch * N_TILE + warp_n * 32 +
                           (int)(lu >> 1) * 8 + tig * 2 + (int)(lu & 1);
                float hb = fmaxf(best[ri], m1);
                b2[ri] = fminf(fminf(b2[ri], m2), hb);
                if (m1 < best[ri]) { best[ri] = m1; bidx[ri] = code; }
            }
    }

    // quad reduce (4 tig lanes share each row)
    #pragma unroll
    for (int ri = 0; ri < 8; ri++) {
        float s = best[ri], t = b2[ri]; int i = bidx[ri];
        #pragma unroll
        for (int m = 1; m <= 2; m <<= 1) {
            float so = __shfl_xor_sync(0xFFFFFFFFu, s, m);
            float to = __shfl_xor_sync(0xFFFFFFFFu, t, m);
            int   io = __shfl_xor_sync(0xFFFFFFFFu, i, m);
            float hb  = fmaxf(s, so);
            float nb2 = fminf(fminf(t, to), hb);
            if (so < s || (so == s && io < i)) { s = so; i = io; }
            t = nb2;
        }
        best[ri] = s; b2[ri] = t; bidx[ri] = i;
    }

    // cross-warp_n merge buffers alias the (now dead) A smem region
    float* m_bst = (float*)smraw;                    // [4][256]
    float* m_b2  = m_bst + 4 * M_TILE;               // [4][256]
    int*   m_bi  = (int*)(m_b2 + 4 * M_TILE);        // [4][256]
    __syncthreads();   // all ldsm of A done before overwrite
    if (tig == 0) {
        #pragma unroll
        for (int ri = 0; ri < 8; ri++) {
            int row = warp_m * 64 + (ri >> 1) * 16 + (ri & 1) * 8 + g;
            m_bst[warp_n * M_TILE + row] = best[ri];
            m_b2 [warp_n * M_TILE + row] = b2[ri];
            m_bi [warp_n * M_TILE + row] = bidx[ri];
        }
    }
    __syncthreads();

    if (tid < M_TILE) {
        float fb = m_bst[tid], ft = m_b2[tid];
        int   fi = m_bi[tid];
        #pragma unroll
        for (int wn = 1; wn < 4; wn++) {
            float sB = m_bst[wn * M_TILE + tid];
            float tB = m_b2 [wn * M_TILE + tid];
            int   iB = m_bi [wn * M_TILE + tid];
            float hb = fmaxf(fb, sB);
            ft = fminf(fminf(ft, tB), hb);
            if (sB < fb || (sB == fb && iB < fi)) { fb = sB; fi = iB; }
        }
        g_ind[row0 + tid] = fi;
        if (ft - fb <= MARGIN) {
            int sl = atomicAdd(&g_namb, 1);
            g_amb[sl] = row0 + tid;
        }
    }
}

// ---------------------------------------------------------------------------
// k_exact: exact fp32 argmin for ambiguous rows. Tiled: 32 rows x 256 codes
// per task, codes/x in smem, coalesced loads, atomicMin(u64) merge.
// ---------------------------------------------------------------------------
__global__ __launch_bounds__(256) void k_exact(const float* __restrict__ x,
                                               const float* __restrict__ emb) {
    extern __shared__ float esm[];
    float* s_e  = esm;                       // 256 x EX_RS
    float* s_x  = esm + 256 * EX_RS;         // 32 x 64
    float* s_e2 = s_x + 32 * 64;             // 256
    int*   s_rid = (int*)(s_e2 + 256);       // 32

    int nn = g_namb;
    int ntasks = ((nn + 31) >> 5) * 8;
    int tid = threadIdx.x;

    for (int task = blockIdx.x; task < ntasks; task += gridDim.x) {
        int rg = task >> 3, cc = task & 7;
        __syncthreads();
        if (tid < 32) {
            int ai = rg * 32 + tid;
            s_rid[tid] = (ai < nn) ? g_amb[ai] : -1;
        }
        for (int i = tid; i < 256 * 16; i += 256) {
            int c = i >> 4, q = i & 15;
            float4 v = *(const float4*)(emb + ((size_t)(cc * 256 + c)) * 64 + q * 4);
            *(float4*)(s_e + c * EX_RS + q * 4) = v;
        }
        s_e2[tid] = g_e2[cc * 256 + tid];
        __syncthreads();
        for (int i = tid; i < 32 * 16; i += 256) {
            int r = i >> 4, q = i & 15;
            int rid = s_rid[r];
            float4 v = (rid >= 0)
                ? *(const float4*)(x + (size_t)rid * 64 + q * 4)
                : make_float4(0.f, 0.f, 0.f, 0.f);
            *(float4*)(s_x + r * 64 + q * 4) = v;
        }
        __syncthreads();

        int row = tid >> 3, cl = tid & 7;
        int rid = s_rid[row];
        if (rid >= 0) {
            float dots[32];
            #pragma unroll
            for (int j = 0; j < 32; j++) dots[j] = 0.f;
            #pragma unroll
            for (int kt = 0; kt < 4; kt++) {
                float xr[16];
                #pragma unroll
                for (int q = 0; q < 4; q++) {
                    float4 v = *(const float4*)(s_x + row * 64 + kt * 16 + q * 4);
                    xr[q*4] = v.x; xr[q*4+1] = v.y; xr[q*4+2] = v.z; xr[q*4+3] = v.w;
                }
                #pragma unroll
                for (int j = 0; j < 32; j++) {
                    const float* ep = s_e + (cl + 8 * j) * EX_RS + kt * 16;
                    #pragma unroll
                    for (int q = 0; q < 4; q++) {
                        float4 ev = *(const float4*)(ep + q * 4);
                        dots[j] += xr[q*4]*ev.x + xr[q*4+1]*ev.y +
                                   xr[q*4+2]*ev.z + xr[q*4+3]*ev.w;
                    }
                }
            }
            float best = 3.4e38f; int bi = 0x7FFFFFFF;
            #pragma unroll
            for (int j = 0; j < 32; j++) {
                int c = cl + 8 * j;
                float sc = s_e2[c] - 2.0f * dots[j];
                int gc = cc * 256 + c;
                if (sc < best || (sc == best && gc < bi)) { best = sc; bi = gc; }
            }
            uint32_t u = __float_as_uint(best);
            u ^= (u & 0x80000000u) ? 0xFFFFFFFFu : 0x80000000u;
            unsigned long long pk =
                ((unsigned long long)u << 32) | (unsigned)bi;
            atomicMin(&g_bestpack[rid], pk);
        }
    }
}

// ---------------------------------------------------------------------------
// k_fix: commit exact argmin for ambiguous rows
// ---------------------------------------------------------------------------
__global__ void k_fix() {
    int nn = g_namb;
    for (int i = blockIdx.x * blockDim.x + threadIdx.x; i < nn;
         i += gridDim.x * blockDim.x) {
        int row = g_amb[i];
        g_ind[row] = (int)(g_bestpack[row] & 0xFFFFFFFFull);
    }
}

// ---------------------------------------------------------------------------
// k_scatter: gather quantize + embed_ind + scatter counts/sums.
// ---------------------------------------------------------------------------
__global__ void k_scatter(const float* __restrict__ x,
                          const float* __restrict__ emb,
                          float* __restrict__ out) {
    int row  = (blockIdx.x * blockDim.x + threadIdx.x) >> 5;
    int lane = threadIdx.x & 31;
    if (row >= N_TOK) return;
    int idx = g_ind[row];

    float2 q = *(const float2*)(emb + (size_t)idx * D + lane * 2);
    *(float2*)(out + OFF_Q + (size_t)row * D + lane * 2) = q;

    float2 xv = *(const float2*)(x + (size_t)row * D + lane * 2);
    atomicAdd(g_sum + (size_t)idx * D + lane * 2,     xv.x);
    atomicAdd(g_sum + (size_t)idx * D + lane * 2 + 1, xv.y);

    if (lane == 0) {
        atomicAdd(g_counts + idx, 1.0f);
        out[OFF_IND + row] = (float)idx;
    }
}

// ---------------------------------------------------------------------------
// k_final: EMA + laplace smoothing + renormalize.
// ---------------------------------------------------------------------------
__global__ __launch_bounds__(1024)
void k_final(const float* __restrict__ cs,
             const float* __restrict__ ea,
             float* __restrict__ out) {
    __shared__ float s_ncs[C_CODES];
    __shared__ float s_red[32];
    int tid = threadIdx.x;

    float local = 0.0f;
    for (int c = tid; c < C_CODES; c += 1024) {
        float v = cs[c] * DECAY_F + g_counts[c] * OMD_F;
        s_ncs[c] = v;
        out[OFF_NCS + c] = v;
        local += v;
    }
    #pragma unroll
    for (int m = 16; m >= 1; m >>= 1)
        local += __shfl_xor_sync(0xFFFFFFFFu, local, m);
    if ((tid & 31) == 0) s_red[tid >> 5] = local;
    __syncthreads();
    if (tid < 32) {
        float v = s_red[tid];
        #pragma unroll
        for (int m = 16; m >= 1; m >>= 1)
            v += __shfl_xor_sync(0xFFFFFFFFu, v, m);
        if (tid == 0) s_red[0] = v;
    }
    __syncthreads();
    float tot   = s_red[0];
    float denom = tot + (float)C_CODES * EPS_F;

    for (int i = tid; i < C_CODES * D; i += 1024) {
        int c = i >> 6;
        float nea = ea[i] * DECAY_F + g_sum[i] * OMD_F;
        out[OFF_NEA + i] = nea;
        float sm = (s_ncs[c] + EPS_F) / denom * tot;
        out[OFF_NE + i] = nea / sm;
    }
}

// ---------------------------------------------------------------------------
// kernel_launch
// ---------------------------------------------------------------------------
extern "C" void kernel_launch(void* const* d_in, const int* in_sizes, int n_in,
                              void* d_out, int out_size) {
    (void)in_sizes; (void)n_in; (void)out_size;
    const float* x   = (const float*)d_in[0];
    const float* emb = (const float*)d_in[1];
    const float* cs  = (const float*)d_in[2];
    const float* ea  = (const float*)d_in[3];
    float* out = (float*)d_out;

    cudaFuncSetAttribute(k_mma, cudaFuncAttributeMaxDynamicSharedMemorySize,
                         SMEM_DYN);
    cudaFuncSetAttribute(k_exact, cudaFuncAttributeMaxDynamicSharedMemorySize,
                         EX_SMEM);

    k_zero<<<512, 256>>>();
    k_prep_b<<<256, 256>>>(emb);
    k_mma<<<N_TOK / M_TILE, NTHR, SMEM_DYN>>>(x);
    k_exact<<<1024, 256, EX_SMEM>>>(x, emb);
    k_fix<<<64, 256>>>();
    k_scatter<<<(N_TOK * 32) / 256, 256>>>(x, emb, out);
    k_final<<<1, 1024>>>(cs, ea, out);
}

// round 9
// speedup vs baseline: 1.0751x; 1.0751x over previous
#include <cuda_runtime.h>
#include <cuda_bf16.h>
#include <cstdint>

// ---------------------------------------------------------------------------
// Problem constants
// ---------------------------------------------------------------------------
#define N_TOK   65536
#define C_CODES 2048
#define D       64
#define KEXT    144                  // [ah|ah|1,1,pad] x [eh|el|e2h,e2l,pad]
#define M_TILE  128
#define N_TILE  64                   // codes per chunk
#define NCHUNK  (C_CODES / N_TILE)   // 32
#define KSTEPS  (KEXT / 16)          // 9
#define MARGIN  0.15f
#define NTHR    256

#define DECAY_F 0.8f
#define OMD_F   0.2f
#define EPS_F   1e-5f

// smem row stride 304 B (76 words ≡ 12 mod 32 -> ldmatrix conflict-free)
#define RSTRIDE      304
#define A_BYTES      (M_TILE * RSTRIDE)      // 38912
#define BCH_BYTES    (N_TILE * RSTRIDE)      // 19456
#define SMEM_B_OFF   A_BYTES
#define SMEM_DYN     (A_BYTES + 2 * BCH_BYTES)   // 77824 -> 2 CTAs/SM

// k_exact smem
#define EX_RS        68
#define EX_SMEM      (256*EX_RS*4 + 32*64*4 + 256*4 + 128)  // 78976

// Output layout (floats), reference return order
#define OFF_Q    0
#define OFF_IND  4194304
#define OFF_NE   4259840
#define OFF_NCS  4390912
#define OFF_NEA  4392960

// ---------------------------------------------------------------------------
// Device scratch
// ---------------------------------------------------------------------------
__device__ __nv_bfloat16 g_B[(size_t)C_CODES * KEXT];
__device__ float g_e2[C_CODES];
__device__ int   g_ind[N_TOK];
__device__ float g_counts[C_CODES];
__device__ float g_sum[C_CODES * D];
__device__ int   g_namb;
__device__ int   g_amb[N_TOK];
__device__ unsigned long long g_bestpack[N_TOK];

// ---------------------------------------------------------------------------
// PTX helpers (baseline sm_80-era only — safe on plain sm_103 target)
// ---------------------------------------------------------------------------
__device__ __forceinline__ uint32_t smem_u32(const void* p) {
    return (uint32_t)__cvta_generic_to_shared(p);
}
__device__ __forceinline__ void cp16(uint32_t saddr, const void* g) {
    asm volatile("cp.async.cg.shared.global [%0], [%1], 16;" :: "r"(saddr), "l"(g));
}
__device__ __forceinline__ void cp_commit() {
    asm volatile("cp.async.commit_group;" ::: "memory");
}
template <int NN> __device__ __forceinline__ void cp_wait() {
    asm volatile("cp.async.wait_group %0;" :: "n"(NN) : "memory");
}
__device__ __forceinline__ void ldsm4(uint32_t* r, uint32_t addr) {
    asm volatile("ldmatrix.sync.aligned.m8n8.x4.shared.b16 {%0,%1,%2,%3}, [%4];"
                 : "=r"(r[0]), "=r"(r[1]), "=r"(r[2]), "=r"(r[3]) : "r"(addr));
}
__device__ __forceinline__ void mma16816(float* d, const uint32_t* a,
                                         uint32_t b0, uint32_t b1) {
    asm volatile(
        "mma.sync.aligned.m16n8k16.row.col.f32.bf16.bf16.f32 "
        "{%0,%1,%2,%3}, {%4,%5,%6,%7}, {%8,%9}, {%0,%1,%2,%3};"
        : "+f"(d[0]), "+f"(d[1]), "+f"(d[2]), "+f"(d[3])
        : "r"(a[0]), "r"(a[1]), "r"(a[2]), "r"(a[3]), "r"(b0), "r"(b1));
}

// ---------------------------------------------------------------------------
// k_zero
// ---------------------------------------------------------------------------
__global__ void k_zero() {
    int i = blockIdx.x * blockDim.x + threadIdx.x;
    if (i == 0) g_namb = 0;
    if (i < C_CODES) g_counts[i] = 0.0f;
    if (i < C_CODES * D) g_sum[i] = 0.0f;
    if (i < N_TOK) g_bestpack[i] = 0xFFFFFFFFFFFFFFFFull;
}

// ---------------------------------------------------------------------------
// k_prep_b: B row = [eh | el | e2h,e2l, 0...] bf16; e2 fp32 for k_exact.
// ---------------------------------------------------------------------------
__global__ void k_prep_b(const float* __restrict__ emb) {
    int c = (blockIdx.x * blockDim.x + threadIdx.x) >> 5;
    int lane = threadIdx.x & 31;
    if (c >= C_CODES) return;
    float2 v = *(const float2*)(emb + (size_t)c * D + lane * 2);
    __nv_bfloat16 h0 = __float2bfloat16(v.x), h1 = __float2bfloat16(v.y);
    __nv_bfloat16 l0 = __float2bfloat16(v.x - __bfloat162float(h0));
    __nv_bfloat16 l1 = __float2bfloat16(v.y - __bfloat162float(h1));
    float sq = v.x * v.x + v.y * v.y;
    #pragma unroll
    for (int m = 16; m >= 1; m >>= 1)
        sq += __shfl_xor_sync(0xFFFFFFFFu, sq, m);
    __nv_bfloat162 hh; hh.x = h0; hh.y = h1;
    __nv_bfloat162 ll; ll.x = l0; ll.y = l1;
    __nv_bfloat162* base = (__nv_bfloat162*)(g_B + (size_t)c * KEXT);
    base[lane] = hh; base[32 + lane] = ll;
    if (lane == 0) {
        __nv_bfloat16 s2h = __float2bfloat16(sq);
        __nv_bfloat16 s2l = __float2bfloat16(sq - __bfloat162float(s2h));
        __nv_bfloat162 z; z.x = __float2bfloat16(0.f); z.y = z.x;
        __nv_bfloat162 e2p; e2p.x = s2h; e2p.y = s2l;
        base[64] = e2p;
        #pragma unroll
        for (int q = 65; q < 72; q++) base[q] = z;
        g_e2[c] = sq;
    }
}

// ---------------------------------------------------------------------------
// k_mma: HMMA split-GEMM (K=144, 2-term + e2 folded) + fused argmin.
// CTA = 256 thr (8 warps, 4m x 2n). 2 CTAs/SM. Double-buffered B.
// ---------------------------------------------------------------------------
__device__ __forceinline__ void issue_b(uint32_t dst, const __nv_bfloat16* src,
                                        int tid) {
    // 64 rows x 18 float4 (288 valid bytes of 304 row)
    #pragma unroll
    for (int it = 0; it < 5; it++) {
        int i = tid + it * NTHR;
        if (i < 64 * 18) {
            int n = i / 18, q = i - n * 18;
            cp16(dst + n * RSTRIDE + q * 16, src + (size_t)n * KEXT + q * 8);
        }
    }
}

extern __shared__ char smraw[];

__global__ __launch_bounds__(NTHR, 2) void k_mma(const float* __restrict__ x) {
    uint32_t A_s = smem_u32(smraw);
    uint32_t B_s = A_s + SMEM_B_OFF;

    __shared__ float s_bst[2][M_TILE];
    __shared__ float s_b2 [2][M_TILE];
    __shared__ int   s_bi [2][M_TILE];

    int tid = threadIdx.x;
    int lane = tid & 31, wid = tid >> 5;
    int warp_m = wid >> 1, warp_n = wid & 1;
    int g   = lane >> 2;
    int tig = lane & 3;
    int row0 = blockIdx.x * M_TILE;

    // prologue: B chunk 0
    issue_b(B_s, g_B, tid);
    cp_commit();

    // build A tile: [bf16(-2x) | residual | 1,1,0...], 128 rows
    {
        const float2* xsrc = (const float2*)(x + (size_t)row0 * D);
        for (int idx = tid; idx < M_TILE * 32; idx += NTHR) {
            int r = idx >> 5, c2 = idx & 31;
            float2 v = xsrc[r * 32 + c2];
            float a0 = -2.0f * v.x, a1 = -2.0f * v.y;
            __nv_bfloat16 h0 = __float2bfloat16(a0), h1 = __float2bfloat16(a1);
            __nv_bfloat16 l0 = __float2bfloat16(a0 - __bfloat162float(h0));
            __nv_bfloat16 l1 = __float2bfloat16(a1 - __bfloat162float(h1));
            __nv_bfloat162 hh; hh.x = h0; hh.y = h1;
            __nv_bfloat162 ll; ll.x = l0; ll.y = l1;
            __nv_bfloat162* rowp = (__nv_bfloat162*)(smraw + r * RSTRIDE);
            rowp[c2] = hh; rowp[32 + c2] = ll;
        }
        // NOTE: A has [ah | ah] pattern for 2-term? No — 2-term is ah*(eh+el):
        // A = [ah | ah], B = [eh | el]. Overwrite cols 64-127 with hh again:
        for (int idx = tid; idx < M_TILE * 32; idx += NTHR) {
            int r = idx >> 5, c2 = idx & 31;
            __nv_bfloat162* rowp = (__nv_bfloat162*)(smraw + r * RSTRIDE);
            rowp[32 + c2] = rowp[c2];
        }
        // cols 128..143: [1,1, 0...]
        for (int r = tid; r < M_TILE; r += NTHR) {
            uint4* tailp = (uint4*)(smraw + r * RSTRIDE + 256);
            tailp[0] = make_uint4(0x3F803F80u, 0u, 0u, 0u);
            tailp[1] = make_uint4(0u, 0u, 0u, 0u);
        }
    }

    int lrow = lane & 15, lsel = lane >> 4;
    uint32_t a_addr0 = A_s + (uint32_t)(warp_m * 32 + lrow) * RSTRIDE + lsel * 16;
    uint32_t a_addr1 = a_addr0 + 16 * RSTRIDE;
    uint32_t b_off0  = (uint32_t)(warp_n * 32 + lrow) * RSTRIDE + lsel * 16;
    uint32_t b_off1  = b_off0 + 16 * RSTRIDE;

    float best[4], b2[4]; int bidx[4];
    #pragma unroll
    for (int i = 0; i < 4; i++) { best[i] = 3.4e38f; b2[i] = 3.4e38f; bidx[i] = 0; }

    for (int ch = 0; ch < NCHUNK; ch++) {
        cp_wait<0>();
        __syncthreads();
        if (ch + 1 < NCHUNK) {
            issue_b(B_s + ((ch + 1) & 1) * BCH_BYTES,
                    g_B + (size_t)(ch + 1) * N_TILE * KEXT, tid);
            cp_commit();
        }

        uint32_t bb = B_s + (ch & 1) * BCH_BYTES;
        uint32_t pb0 = bb + b_off0, pb1 = bb + b_off1;

        float acc[2][4][4];
        #pragma unroll
        for (int mt = 0; mt < 2; mt++)
            #pragma unroll
            for (int nt = 0; nt < 4; nt++)
                #pragma unroll
                for (int q = 0; q < 4; q++) acc[mt][nt][q] = 0.0f;

        #pragma unroll
        for (int ks = 0; ks < KSTEPS; ks++) {
            uint32_t A0[4], A1[4], B0[4], B1[4];
            ldsm4(A0, a_addr0 + ks * 32);
            ldsm4(A1, a_addr1 + ks * 32);
            ldsm4(B0, pb0 + ks * 32);
            ldsm4(B1, pb1 + ks * 32);
            mma16816(acc[0][0], A0, B0[0], B0[2]);
            mma16816(acc[0][1], A0, B0[1], B0[3]);
            mma16816(acc[0][2], A0, B1[0], B1[2]);
            mma16816(acc[0][3], A0, B1[1], B1[3]);
            mma16816(acc[1][0], A1, B0[0], B0[2]);
            mma16816(acc[1][1], A1, B0[1], B0[3]);
            mma16816(acc[1][2], A1, B1[0], B1[2]);
            mma16816(acc[1][3], A1, B1[1], B1[3]);
        }

        // branchless epilogue: 3-bit local idx in mantissa LSBs,
        // per-row-stream (m1, m2) via min/max chains, one unpack per chunk.
        #pragma unroll
        for (int mt = 0; mt < 2; mt++)
            #pragma unroll
            for (int e = 0; e < 2; e++) {
                int ri = mt * 2 + e;
                float m1 = 3.4e38f, m2 = 3.4e38f;
                #pragma unroll
                for (int nt = 0; nt < 4; nt++)
                    #pragma unroll
                    for (int b = 0; b < 2; b++) {
                        float s = acc[mt][nt][e * 2 + b];
                        uint32_t u = (__float_as_uint(s) & ~7u) |
                                     (uint32_t)(nt * 2 + b);
                        float sp = __uint_as_float(u);
                        m2 = fminf(m2, fmaxf(m1, sp));
                        m1 = fminf(m1, sp);
                    }
                uint32_t lu = __float_as_uint(m1) & 7u;
                int code = ch * N_TILE + warp_n * 32 +
                           (int)(lu >> 1) * 8 + tig * 2 + (int)(lu & 1);
                float hb = fmaxf(best[ri], m1);
                b2[ri] = fminf(fminf(b2[ri], m2), hb);
                if (m1 < best[ri]) { best[ri] = m1; bidx[ri] = code; }
            }
    }

    // quad reduce (4 tig lanes share each row)
    #pragma unroll
    for (int ri = 0; ri < 4; ri++) {
        float s = best[ri], t = b2[ri]; int i = bidx[ri];
        #pragma unroll
        for (int m = 1; m <= 2; m <<= 1) {
            float so = __shfl_xor_sync(0xFFFFFFFFu, s, m);
            float to = __shfl_xor_sync(0xFFFFFFFFu, t, m);
            int   io = __shfl_xor_sync(0xFFFFFFFFu, i, m);
            float hb  = fmaxf(s, so);
            float nb2 = fminf(fminf(t, to), hb);
            if (so < s || (so == s && io < i)) { s = so; i = io; }
            t = nb2;
        }
        best[ri] = s; b2[ri] = t; bidx[ri] = i;
    }
    if (tig == 0) {
        #pragma unroll
        for (int ri = 0; ri < 4; ri++) {
            int row = warp_m * 32 + (ri >> 1) * 16 + (ri & 1) * 8 + g;
            s_bst[warp_n][row] = best[ri];
            s_b2 [warp_n][row] = b2[ri];
            s_bi [warp_n][row] = bidx[ri];
        }
    }
    __syncthreads();

    if (tid < M_TILE) {
        float sA = s_bst[0][tid], sB = s_bst[1][tid];
        float tA = s_b2[0][tid],  tB = s_b2[1][tid];
        int   iA = s_bi[0][tid],  iB = s_bi[1][tid];
        float hb  = fmaxf(sA, sB);
        float fb2 = fminf(fminf(tA, tB), hb);
        float fb; int fi;
        if (sB < sA || (sB == sA && iB < iA)) { fb = sB; fi = iB; }
        else                                  { fb = sA; fi = iA; }
        g_ind[row0 + tid] = fi;
        if (fb2 - fb <= MARGIN) {
            int sl = atomicAdd(&g_namb, 1);
            g_amb[sl] = row0 + tid;
        }
    }
}

// ---------------------------------------------------------------------------
// k_exact: exact fp32 argmin for ambiguous rows. Tiled: 32 rows x 256 codes
// per task, codes/x in smem, coalesced loads, atomicMin(u64) merge.
// ---------------------------------------------------------------------------
__global__ __launch_bounds__(256) void k_exact(const float* __restrict__ x,
                                               const float* __restrict__ emb) {
    extern __shared__ float esm[];
    float* s_e  = esm;                       // 256 x EX_RS
    float* s_x  = esm + 256 * EX_RS;         // 32 x 64
    float* s_e2 = s_x + 32 * 64;             // 256
    int*   s_rid = (int*)(s_e2 + 256);       // 32

    int nn = g_namb;
    int ntasks = ((nn + 31) >> 5) * 8;
    int tid = threadIdx.x;

    for (int task = blockIdx.x; task < ntasks; task += gridDim.x) {
        int rg = task >> 3, cc = task & 7;
        __syncthreads();
        if (tid < 32) {
            int ai = rg * 32 + tid;
            s_rid[tid] = (ai < nn) ? g_amb[ai] : -1;
        }
        for (int i = tid; i < 256 * 16; i += 256) {
            int c = i >> 4, q = i & 15;
            float4 v = *(const float4*)(emb + ((size_t)(cc * 256 + c)) * 64 + q * 4);
            *(float4*)(s_e + c * EX_RS + q * 4) = v;
        }
        s_e2[tid] = g_e2[cc * 256 + tid];
        __syncthreads();
        for (int i = tid; i < 32 * 16; i += 256) {
            int r = i >> 4, q = i & 15;
            int rid = s_rid[r];
            float4 v = (rid >= 0)
                ? *(const float4*)(x + (size_t)rid * 64 + q * 4)
                : make_float4(0.f, 0.f, 0.f, 0.f);
            *(float4*)(s_x + r * 64 + q * 4) = v;
        }
        __syncthreads();

        int row = tid >> 3, cl = tid & 7;
        int rid = s_rid[row];
        if (rid >= 0) {
            float dots[32];
            #pragma unroll
            for (int j = 0; j < 32; j++) dots[j] = 0.f;
            #pragma unroll
            for (int kt = 0; kt < 4; kt++) {
                float xr[16];
                #pragma unroll
                for (int q = 0; q < 4; q++) {
                    float4 v = *(const float4*)(s_x + row * 64 + kt * 16 + q * 4);
                    xr[q*4] = v.x; xr[q*4+1] = v.y; xr[q*4+2] = v.z; xr[q*4+3] = v.w;
                }
                #pragma unroll
                for (int j = 0; j < 32; j++) {
                    const float* ep = s_e + (cl + 8 * j) * EX_RS + kt * 16;
                    #pragma unroll
                    for (int q = 0; q < 4; q++) {
                        float4 ev = *(const float4*)(ep + q * 4);
                        dots[j] += xr[q*4]*ev.x + xr[q*4+1]*ev.y +
                                   xr[q*4+2]*ev.z + xr[q*4+3]*ev.w;
                    }
                }
            }
            float best = 3.4e38f; int bi = 0x7FFFFFFF;
            #pragma unroll
            for (int j = 0; j < 32; j++) {
                int c = cl + 8 * j;
                float sc = s_e2[c] - 2.0f * dots[j];
                int gc = cc * 256 + c;
                if (sc < best || (sc == best && gc < bi)) { best = sc; bi = gc; }
            }
            uint32_t u = __float_as_uint(best);
            u ^= (u & 0x80000000u) ? 0xFFFFFFFFu : 0x80000000u;
            unsigned long long pk =
                ((unsigned long long)u << 32) | (unsigned)bi;
            atomicMin(&g_bestpack[rid], pk);
        }
    }
}

// ---------------------------------------------------------------------------
// k_fix: commit exact argmin for ambiguous rows
// ---------------------------------------------------------------------------
__global__ void k_fix() {
    int nn = g_namb;
    for (int i = blockIdx.x * blockDim.x + threadIdx.x; i < nn;
         i += gridDim.x * blockDim.x) {
        int row = g_amb[i];
        g_ind[row] = (int)(g_bestpack[row] & 0xFFFFFFFFull);
    }
}

// ---------------------------------------------------------------------------
// k_scatter: gather quantize + embed_ind + scatter counts/sums.
// ---------------------------------------------------------------------------
__global__ void k_scatter(const float* __restrict__ x,
                          const float* __restrict__ emb,
                          float* __restrict__ out) {
    int row  = (blockIdx.x * blockDim.x + threadIdx.x) >> 5;
    int lane = threadIdx.x & 31;
    if (row >= N_TOK) return;
    int idx = g_ind[row];

    float2 q = *(const float2*)(emb + (size_t)idx * D + lane * 2);
    *(float2*)(out + OFF_Q + (size_t)row * D + lane * 2) = q;

    float2 xv = *(const float2*)(x + (size_t)row * D + lane * 2);
    atomicAdd(g_sum + (size_t)idx * D + lane * 2,     xv.x);
    atomicAdd(g_sum + (size_t)idx * D + lane * 2 + 1, xv.y);

    if (lane == 0) {
        atomicAdd(g_counts + idx, 1.0f);
        out[OFF_IND + row] = (float)idx;
    }
}

// ---------------------------------------------------------------------------
// k_final: EMA + laplace smoothing + renormalize.
// ---------------------------------------------------------------------------
__global__ __launch_bounds__(1024)
void k_final(const float* __restrict__ cs,
             const float* __restrict__ ea,
             float* __restrict__ out) {
    __shared__ float s_ncs[C_CODES];
    __shared__ float s_red[32];
    int tid = threadIdx.x;

    float local = 0.0f;
    for (int c = tid; c < C_CODES; c += 1024) {
        float v = cs[c] * DECAY_F + g_counts[c] * OMD_F;
        s_ncs[c] = v;
        out[OFF_NCS + c] = v;
        local += v;
    }
    #pragma unroll
    for (int m = 16; m >= 1; m >>= 1)
        local += __shfl_xor_sync(0xFFFFFFFFu, local, m);
    if ((tid & 31) == 0) s_red[tid >> 5] = local;
    __syncthreads();
    if (tid < 32) {
        float v = s_red[tid];
        #pragma unroll
        for (int m = 16; m >= 1; m >>= 1)
            v += __shfl_xor_sync(0xFFFFFFFFu, v, m);
        if (tid == 0) s_red[0] = v;
    }
    __syncthreads();
    float tot   = s_red[0];
    float denom = tot + (float)C_CODES * EPS_F;

    for (int i = tid; i < C_CODES * D; i += 1024) {
        int c = i >> 6;
        float nea = ea[i] * DECAY_F + g_sum[i] * OMD_F;
        out[OFF_NEA + i] = nea;
        float sm = (s_ncs[c] + EPS_F) / denom * tot;
        out[OFF_NE + i] = nea / sm;
    }
}

// ---------------------------------------------------------------------------
// kernel_launch
// ---------------------------------------------------------------------------
extern "C" void kernel_launch(void* const* d_in, const int* in_sizes, int n_in,
                              void* d_out, int out_size) {
    (void)in_sizes; (void)n_in; (void)out_size;
    const float* x   = (const float*)d_in[0];
    const float* emb = (const float*)d_in[1];
    const float* cs  = (const float*)d_in[2];
    const float* ea  = (const float*)d_in[3];
    float* out = (float*)d_out;

    cudaFuncSetAttribute(k_mma, cudaFuncAttributeMaxDynamicSharedMemorySize,
                         SMEM_DYN);
    cudaFuncSetAttribute(k_exact, cudaFuncAttributeMaxDynamicSharedMemorySize,
                         EX_SMEM);

    k_zero<<<512, 256>>>();
    k_prep_b<<<256, 256>>>(emb);
    k_mma<<<N_TOK / M_TILE, NTHR, SMEM_DYN>>>(x);
    k_exact<<<1024, 256, EX_SMEM>>>(x, emb);
    k_fix<<<64, 256>>>();
    k_scatter<<<(N_TOK * 32) / 256, 256>>>(x, emb, out);
    k_final<<<1, 1024>>>(cs, ea, out);
}

// round 13
// speedup vs baseline: 1.1340x; 1.0548x over previous
#include <cuda_runtime.h>
#include <cuda_bf16.h>
#include <cstdint>

// ---------------------------------------------------------------------------
// Problem constants
// ---------------------------------------------------------------------------
#define N_TOK   65536
#define C_CODES 2048
#define D       64
#define KEXT    144                  // [ah|ah|1,1,pad] x [eh|el|e2h,e2l,pad]
#define M_TILE  128
#define N_TILE  64                   // codes per chunk
#define NCHUNK  (C_CODES / N_TILE)   // 32
#define KSTEPS  (KEXT / 16)          // 9
#define MARGIN  0.15f
#define NTHR    256

#define DECAY_F 0.8f
#define OMD_F   0.2f
#define EPS_F   1e-5f

// smem row stride 304 B (76 words ≡ 12 mod 32 -> ldmatrix conflict-free)
#define RSTRIDE      304
#define A_BYTES      (M_TILE * RSTRIDE)      // 38912
#define BCH_BYTES    (N_TILE * RSTRIDE)      // 19456
#define SMEM_B_OFF   A_BYTES
#define SMEM_DYN     (A_BYTES + 2 * BCH_BYTES)   // 77824 -> 2 CTAs/SM

// k_exact smem
#define EX_RS        68
#define EX_SMEM      (256*EX_RS*4 + 32*64*4 + 256*4 + 128)  // 78976

// Output layout (floats), reference return order
#define OFF_Q    0
#define OFF_IND  4194304
#define OFF_NE   4259840
#define OFF_NCS  4390912
#define OFF_NEA  4392960

// ---------------------------------------------------------------------------
// Device scratch
// ---------------------------------------------------------------------------
__device__ __nv_bfloat16 g_B[(size_t)C_CODES * KEXT];
__device__ float g_e2[C_CODES];
__device__ int   g_ind[N_TOK];
__device__ float g_counts[C_CODES];
__device__ float g_sum[C_CODES * D];
__device__ int   g_namb;
__device__ int   g_amb[N_TOK];
__device__ unsigned long long g_bestpack[N_TOK];

// ---------------------------------------------------------------------------
// PTX helpers (baseline sm_80-era only — safe on plain sm_103 target)
// ---------------------------------------------------------------------------
__device__ __forceinline__ uint32_t smem_u32(const void* p) {
    return (uint32_t)__cvta_generic_to_shared(p);
}
__device__ __forceinline__ void cp16(uint32_t saddr, const void* g) {
    asm volatile("cp.async.cg.shared.global [%0], [%1], 16;" :: "r"(saddr), "l"(g));
}
__device__ __forceinline__ void cp_commit() {
    asm volatile("cp.async.commit_group;" ::: "memory");
}
template <int NN> __device__ __forceinline__ void cp_wait() {
    asm volatile("cp.async.wait_group %0;" :: "n"(NN) : "memory");
}
__device__ __forceinline__ void ldsm4(uint32_t* r, uint32_t addr) {
    asm volatile("ldmatrix.sync.aligned.m8n8.x4.shared.b16 {%0,%1,%2,%3}, [%4];"
                 : "=r"(r[0]), "=r"(r[1]), "=r"(r[2]), "=r"(r[3]) : "r"(addr));
}
__device__ __forceinline__ void mma16816(float* d, const uint32_t* a,
                                         uint32_t b0, uint32_t b1) {
    asm volatile(
        "mma.sync.aligned.m16n8k16.row.col.f32.bf16.bf16.f32 "
        "{%0,%1,%2,%3}, {%4,%5,%6,%7}, {%8,%9}, {%0,%1,%2,%3};"
        : "+f"(d[0]), "+f"(d[1]), "+f"(d[2]), "+f"(d[3])
        : "r"(a[0]), "r"(a[1]), "r"(a[2]), "r"(a[3]), "r"(b0), "r"(b1));
}

// ---------------------------------------------------------------------------
// k_zero
// ---------------------------------------------------------------------------
__global__ void k_zero() {
    int i = blockIdx.x * blockDim.x + threadIdx.x;
    if (i == 0) g_namb = 0;
    if (i < C_CODES) g_counts[i] = 0.0f;
    if (i < C_CODES * D) g_sum[i] = 0.0f;
    if (i < N_TOK) g_bestpack[i] = 0xFFFFFFFFFFFFFFFFull;
}

// ---------------------------------------------------------------------------
// k_prep_b: B row = [eh | el | e2h,e2l, 0...] bf16; e2 fp32 for k_exact.
// ---------------------------------------------------------------------------
__global__ void k_prep_b(const float* __restrict__ emb) {
    int c = (blockIdx.x * blockDim.x + threadIdx.x) >> 5;
    int lane = threadIdx.x & 31;
    if (c >= C_CODES) return;
    float2 v = *(const float2*)(emb + (size_t)c * D + lane * 2);
    __nv_bfloat16 h0 = __float2bfloat16(v.x), h1 = __float2bfloat16(v.y);
    __nv_bfloat16 l0 = __float2bfloat16(v.x - __bfloat162float(h0));
    __nv_bfloat16 l1 = __float2bfloat16(v.y - __bfloat162float(h1));
    float sq = v.x * v.x + v.y * v.y;
    #pragma unroll
    for (int m = 16; m >= 1; m >>= 1)
        sq += __shfl_xor_sync(0xFFFFFFFFu, sq, m);
    __nv_bfloat162 hh; hh.x = h0; hh.y = h1;
    __nv_bfloat162 ll; ll.x = l0; ll.y = l1;
    __nv_bfloat162* base = (__nv_bfloat162*)(g_B + (size_t)c * KEXT);
    base[lane] = hh; base[32 + lane] = ll;
    if (lane == 0) {
        __nv_bfloat16 s2h = __float2bfloat16(sq);
        __nv_bfloat16 s2l = __float2bfloat16(sq - __bfloat162float(s2h));
        __nv_bfloat162 z; z.x = __float2bfloat16(0.f); z.y = z.x;
        __nv_bfloat162 e2p; e2p.x = s2h; e2p.y = s2l;
        base[64] = e2p;
        #pragma unroll
        for (int q = 65; q < 72; q++) base[q] = z;
        g_e2[c] = sq;
    }
}

// ---------------------------------------------------------------------------
// k_mma: HMMA split-GEMM (K=144) + fused argmin + FUSED SCATTER.
// CTA = 256 thr (8 warps, 4m x 2n). 2 CTAs/SM. Double-buffered B.
// After the merge, this CTA owns rows [row0, row0+128): writes quantize,
// embed_ind, and count/sum atomics using the approximate index; k_fix
// patches the (rare) rows where the exact index differs.
// ---------------------------------------------------------------------------
__device__ __forceinline__ void issue_b(uint32_t dst, const __nv_bfloat16* src,
                                        int tid) {
    // 64 rows x 18 float4 (288 valid bytes of 304 row)
    #pragma unroll
    for (int it = 0; it < 5; it++) {
        int i = tid + it * NTHR;
        if (i < 64 * 18) {
            int n = i / 18, q = i - n * 18;
            cp16(dst + n * RSTRIDE + q * 16, src + (size_t)n * KEXT + q * 8);
        }
    }
}

extern __shared__ char smraw[];

__global__ __launch_bounds__(NTHR, 2) void k_mma(const float* __restrict__ x,
                                                 const float* __restrict__ emb,
                                                 float* __restrict__ out) {
    uint32_t A_s = smem_u32(smraw);
    uint32_t B_s = A_s + SMEM_B_OFF;

    __shared__ float s_bst[2][M_TILE];
    __shared__ float s_b2 [2][M_TILE];
    __shared__ int   s_bi [2][M_TILE];
    __shared__ int   s_fi [M_TILE];

    int tid = threadIdx.x;
    int lane = tid & 31, wid = tid >> 5;
    int warp_m = wid >> 1, warp_n = wid & 1;
    int g   = lane >> 2;
    int tig = lane & 3;
    int row0 = blockIdx.x * M_TILE;

    // prologue: B chunk 0
    issue_b(B_s, g_B, tid);
    cp_commit();

    // build A tile: [ah | ah | 1,1,0...], 128 rows (2-term: residual unused)
    {
        const float2* xsrc = (const float2*)(x + (size_t)row0 * D);
        for (int idx = tid; idx < M_TILE * 32; idx += NTHR) {
            int r = idx >> 5, c2 = idx & 31;
            float2 v = xsrc[r * 32 + c2];
            __nv_bfloat16 h0 = __float2bfloat16(-2.0f * v.x);
            __nv_bfloat16 h1 = __float2bfloat16(-2.0f * v.y);
            __nv_bfloat162 hh; hh.x = h0; hh.y = h1;
            __nv_bfloat162* rowp = (__nv_bfloat162*)(smraw + r * RSTRIDE);
            rowp[c2] = hh; rowp[32 + c2] = hh;
        }
        for (int r = tid; r < M_TILE; r += NTHR) {
            uint4* tailp = (uint4*)(smraw + r * RSTRIDE + 256);
            tailp[0] = make_uint4(0x3F803F80u, 0u, 0u, 0u);
            tailp[1] = make_uint4(0u, 0u, 0u, 0u);
        }
    }

    int lrow = lane & 15, lsel = lane >> 4;
    uint32_t a_addr0 = A_s + (uint32_t)(warp_m * 32 + lrow) * RSTRIDE + lsel * 16;
    uint32_t a_addr1 = a_addr0 + 16 * RSTRIDE;
    uint32_t b_off0  = (uint32_t)(warp_n * 32 + lrow) * RSTRIDE + lsel * 16;
    uint32_t b_off1  = b_off0 + 16 * RSTRIDE;

    float best[4], b2[4]; int bidx[4];
    #pragma unroll
    for (int i = 0; i < 4; i++) { best[i] = 3.4e38f; b2[i] = 3.4e38f; bidx[i] = 0; }

    for (int ch = 0; ch < NCHUNK; ch++) {
        cp_wait<0>();
        __syncthreads();
        if (ch + 1 < NCHUNK) {
            issue_b(B_s + ((ch + 1) & 1) * BCH_BYTES,
                    g_B + (size_t)(ch + 1) * N_TILE * KEXT, tid);
            cp_commit();
        }

        uint32_t bb = B_s + (ch & 1) * BCH_BYTES;
        uint32_t pb0 = bb + b_off0, pb1 = bb + b_off1;

        float acc[2][4][4];
        #pragma unroll
        for (int mt = 0; mt < 2; mt++)
            #pragma unroll
            for (int nt = 0; nt < 4; nt++)
                #pragma unroll
                for (int q = 0; q < 4; q++) acc[mt][nt][q] = 0.0f;

        #pragma unroll
        for (int ks = 0; ks < KSTEPS; ks++) {
            uint32_t A0[4], A1[4], B0[4], B1[4];
            ldsm4(A0, a_addr0 + ks * 32);
            ldsm4(A1, a_addr1 + ks * 32);
            ldsm4(B0, pb0 + ks * 32);
            ldsm4(B1, pb1 + ks * 32);
            mma16816(acc[0][0], A0, B0[0], B0[2]);
            mma16816(acc[0][1], A0, B0[1], B0[3]);
            mma16816(acc[0][2], A0, B1[0], B1[2]);
            mma16816(acc[0][3], A0, B1[1], B1[3]);
            mma16816(acc[1][0], A1, B0[0], B0[2]);
            mma16816(acc[1][1], A1, B0[1], B0[3]);
            mma16816(acc[1][2], A1, B1[0], B1[2]);
            mma16816(acc[1][3], A1, B1[1], B1[3]);
        }

        // branchless epilogue: 3-bit local idx in mantissa LSBs,
        // per-row-stream (m1, m2) via min/max chains, one unpack per chunk.
        #pragma unroll
        for (int mt = 0; mt < 2; mt++)
            #pragma unroll
            for (int e = 0; e < 2; e++) {
                int ri = mt * 2 + e;
                float m1 = 3.4e38f, m2 = 3.4e38f;
                #pragma unroll
                for (int nt = 0; nt < 4; nt++)
                    #pragma unroll
                    for (int b = 0; b < 2; b++) {
                        float s = acc[mt][nt][e * 2 + b];
                        uint32_t u = (__float_as_uint(s) & ~7u) |
                                     (uint32_t)(nt * 2 + b);
                        float sp = __uint_as_float(u);
                        m2 = fminf(m2, fmaxf(m1, sp));
                        m1 = fminf(m1, sp);
                    }
                uint32_t lu = __float_as_uint(m1) & 7u;
                int code = ch * N_TILE + warp_n * 32 +
                           (int)(lu >> 1) * 8 + tig * 2 + (int)(lu & 1);
                float hb = fmaxf(best[ri], m1);
                b2[ri] = fminf(fminf(b2[ri], m2), hb);
                if (m1 < best[ri]) { best[ri] = m1; bidx[ri] = code; }
            }
    }

    // quad reduce (4 tig lanes share each row)
    #pragma unroll
    for (int ri = 0; ri < 4; ri++) {
        float s = best[ri], t = b2[ri]; int i = bidx[ri];
        #pragma unroll
        for (int m = 1; m <= 2; m <<= 1) {
            float so = __shfl_xor_sync(0xFFFFFFFFu, s, m);
            float to = __shfl_xor_sync(0xFFFFFFFFu, t, m);
            int   io = __shfl_xor_sync(0xFFFFFFFFu, i, m);
            float hb  = fmaxf(s, so);
            float nb2 = fminf(fminf(t, to), hb);
            if (so < s || (so == s && io < i)) { s = so; i = io; }
            t = nb2;
        }
        best[ri] = s; b2[ri] = t; bidx[ri] = i;
    }
    if (tig == 0) {
        #pragma unroll
        for (int ri = 0; ri < 4; ri++) {
            int row = warp_m * 32 + (ri >> 1) * 16 + (ri & 1) * 8 + g;
            s_bst[warp_n][row] = best[ri];
            s_b2 [warp_n][row] = b2[ri];
            s_bi [warp_n][row] = bidx[ri];
        }
    }
    __syncthreads();

    if (tid < M_TILE) {
        float sA = s_bst[0][tid], sB = s_bst[1][tid];
        float tA = s_b2[0][tid],  tB = s_b2[1][tid];
        int   iA = s_bi[0][tid],  iB = s_bi[1][tid];
        float hb  = fmaxf(sA, sB);
        float fb2 = fminf(fminf(tA, tB), hb);
        float fb; int fi;
        if (sB < sA || (sB == sA && iB < iA)) { fb = sB; fi = iB; }
        else                                  { fb = sA; fi = iA; }
        s_fi[tid] = fi;
        g_ind[row0 + tid] = fi;
        out[OFF_IND + row0 + tid] = (float)fi;
        atomicAdd(g_counts + fi, 1.0f);
        if (fb2 - fb <= MARGIN) {
            int sl = atomicAdd(&g_namb, 1);
            g_amb[sl] = row0 + tid;
        }
    }
    __syncthreads();

    // fused scatter: warp per row — gather quantize, scatter feature sums
    for (int r = wid; r < M_TILE; r += 8) {
        int idx = s_fi[r];
        float2 q = *(const float2*)(emb + (size_t)idx * D + lane * 2);
        *(float2*)(out + OFF_Q + (size_t)(row0 + r) * D + lane * 2) = q;
        float2 xv = *(const float2*)(x + (size_t)(row0 + r) * D + lane * 2);
        atomicAdd(g_sum + (size_t)idx * D + lane * 2,     xv.x);
        atomicAdd(g_sum + (size_t)idx * D + lane * 2 + 1, xv.y);
    }
}

// ---------------------------------------------------------------------------
// k_exact: exact fp32 argmin for ambiguous rows. Tiled: 32 rows x 256 codes
// per task, codes/x in smem, coalesced loads, atomicMin(u64) merge.
// ---------------------------------------------------------------------------
__global__ __launch_bounds__(256, 2) void k_exact(const float* __restrict__ x,
                                                  const float* __restrict__ emb) {
    extern __shared__ float esm[];
    float* s_e  = esm;                       // 256 x EX_RS
    float* s_x  = esm + 256 * EX_RS;         // 32 x 64
    float* s_e2 = s_x + 32 * 64;             // 256
    int*   s_rid = (int*)(s_e2 + 256);       // 32

    int nn = g_namb;
    int ntasks = ((nn + 31) >> 5) * 8;
    int tid = threadIdx.x;

    for (int task = blockIdx.x; task < ntasks; task += gridDim.x) {
        int rg = task >> 3, cc = task & 7;
        __syncthreads();
        if (tid < 32) {
            int ai = rg * 32 + tid;
            s_rid[tid] = (ai < nn) ? g_amb[ai] : -1;
        }
        for (int i = tid; i < 256 * 16; i += 256) {
            int c = i >> 4, q = i & 15;
            float4 v = *(const float4*)(emb + ((size_t)(cc * 256 + c)) * 64 + q * 4);
            *(float4*)(s_e + c * EX_RS + q * 4) = v;
        }
        s_e2[tid] = g_e2[cc * 256 + tid];
        __syncthreads();
        for (int i = tid; i < 32 * 16; i += 256) {
            int r = i >> 4, q = i & 15;
            int rid = s_rid[r];
            float4 v = (rid >= 0)
                ? *(const float4*)(x + (size_t)rid * 64 + q * 4)
                : make_float4(0.f, 0.f, 0.f, 0.f);
            *(float4*)(s_x + r * 64 + q * 4) = v;
        }
        __syncthreads();

        int row = tid >> 3, cl = tid & 7;
        int rid = s_rid[row];
        if (rid >= 0) {
            float dots[32];
            #pragma unroll
            for (int j = 0; j < 32; j++) dots[j] = 0.f;
            #pragma unroll
            for (int kt = 0; kt < 4; kt++) {
                float xr[16];
                #pragma unroll
                for (int q = 0; q < 4; q++) {
                    float4 v = *(const float4*)(s_x + row * 64 + kt * 16 + q * 4);
                    xr[q*4] = v.x; xr[q*4+1] = v.y; xr[q*4+2] = v.z; xr[q*4+3] = v.w;
                }
                #pragma unroll
                for (int j = 0; j < 32; j++) {
                    const float* ep = s_e + (cl + 8 * j) * EX_RS + kt * 16;
                    #pragma unroll
                    for (int q = 0; q < 4; q++) {
                        float4 ev = *(const float4*)(ep + q * 4);
                        dots[j] += xr[q*4]*ev.x + xr[q*4+1]*ev.y +
                                   xr[q*4+2]*ev.z + xr[q*4+3]*ev.w;
                    }
                }
            }
            float best = 3.4e38f; int bi = 0x7FFFFFFF;
            #pragma unroll
            for (int j = 0; j < 32; j++) {
                int c = cl + 8 * j;
                float sc = s_e2[c] - 2.0f * dots[j];
                int gc = cc * 256 + c;
                if (sc < best || (sc == best && gc < bi)) { best = sc; bi = gc; }
            }
            uint32_t u = __float_as_uint(best);
            u ^= (u & 0x80000000u) ? 0xFFFFFFFFu : 0x80000000u;
            unsigned long long pk =
                ((unsigned long long)u << 32) | (unsigned)bi;
            atomicMin(&g_bestpack[rid], pk);
        }
    }
}

// ---------------------------------------------------------------------------
// k_fix: patch rows where exact argmin differs from the approx one used by
// the fused scatter — rewrite ind/quantize, compensate count/sum atomics.
// ---------------------------------------------------------------------------
__global__ void k_fix(const float* __restrict__ x,
                      const float* __restrict__ emb,
                      float* __restrict__ out) {
    int nn = g_namb;
    int w = (blockIdx.x * blockDim.x + threadIdx.x) >> 5;
    int lane = threadIdx.x & 31;
    int nw = (gridDim.x * blockDim.x) >> 5;
    for (int i = w; i < nn; i += nw) {
        int row = g_amb[i];
        int newi = (int)(g_bestpack[row] & 0xFFFFFFFFull);
        int oldi = g_ind[row];
        if (newi == oldi) continue;
        if (lane == 0) {
            g_ind[row] = newi;
            out[OFF_IND + row] = (float)newi;
            atomicAdd(g_counts + oldi, -1.0f);
            atomicAdd(g_counts + newi,  1.0f);
        }
        float2 q = *(const float2*)(emb + (size_t)newi * D + lane * 2);
        *(float2*)(out + OFF_Q + (size_t)row * D + lane * 2) = q;
        float2 xv = *(const float2*)(x + (size_t)row * D + lane * 2);
        atomicAdd(g_sum + (size_t)oldi * D + lane * 2,     -xv.x);
        atomicAdd(g_sum + (size_t)oldi * D + lane * 2 + 1, -xv.y);
        atomicAdd(g_sum + (size_t)newi * D + lane * 2,      xv.x);
        atomicAdd(g_sum + (size_t)newi * D + lane * 2 + 1,  xv.y);
    }
}

// ---------------------------------------------------------------------------
// k_final: EMA + laplace smoothing + renormalize.
// ---------------------------------------------------------------------------
__global__ __launch_bounds__(1024)
void k_final(const float* __restrict__ cs,
             const float* __restrict__ ea,
             float* __restrict__ out) {
    __shared__ float s_ncs[C_CODES];
    __shared__ float s_red[32];
    int tid = threadIdx.x;

    float local = 0.0f;
    for (int c = tid; c < C_CODES; c += 1024) {
        float v = cs[c] * DECAY_F + g_counts[c] * OMD_F;
        s_ncs[c] = v;
        out[OFF_NCS + c] = v;
        local += v;
    }
    #pragma unroll
    for (int m = 16; m >= 1; m >>= 1)
        local += __shfl_xor_sync(0xFFFFFFFFu, local, m);
    if ((tid & 31) == 0) s_red[tid >> 5] = local;
    __syncthreads();
    if (tid < 32) {
        float v = s_red[tid];
        #pragma unroll
        for (int m = 16; m >= 1; m >>= 1)
            v += __shfl_xor_sync(0xFFFFFFFFu, v, m);
        if (tid == 0) s_red[0] = v;
    }
    __syncthreads();
    float tot   = s_red[0];
    float denom = tot + (float)C_CODES * EPS_F;

    for (int i = tid; i < C_CODES * D; i += 1024) {
        int c = i >> 6;
        float nea = ea[i] * DECAY_F + g_sum[i] * OMD_F;
        out[OFF_NEA + i] = nea;
        float sm = (s_ncs[c] + EPS_F) / denom * tot;
        out[OFF_NE + i] = nea / sm;
    }
}

// ---------------------------------------------------------------------------
// kernel_launch
// ---------------------------------------------------------------------------
extern "C" void kernel_launch(void* const* d_in, const int* in_sizes, int n_in,
                              void* d_out, int out_size) {
    (void)in_sizes; (void)n_in; (void)out_size;
    const float* x   = (const float*)d_in[0];
    const float* emb = (const float*)d_in[1];
    const float* cs  = (const float*)d_in[2];
    const float* ea  = (const float*)d_in[3];
    float* out = (float*)d_out;

    cudaFuncSetAttribute(k_mma, cudaFuncAttributeMaxDynamicSharedMemorySize,
                         SMEM_DYN);
    cudaFuncSetAttribute(k_exact, cudaFuncAttributeMaxDynamicSharedMemorySize,
                         EX_SMEM);

    k_zero<<<512, 256>>>();
    k_prep_b<<<256, 256>>>(emb);
    k_mma<<<N_TOK / M_TILE, NTHR, SMEM_DYN>>>(x, emb, out);
    k_exact<<<1024, 256, EX_SMEM>>>(x, emb);
    k_fix<<<64, 256>>>(x, emb, out);
    k_final<<<1, 1024>>>(cs, ea, out);
}

// round 14
// speedup vs baseline: 1.2943x; 1.1413x over previous
#include <cuda_runtime.h>
#include <cuda_bf16.h>
#include <cstdint>

// ---------------------------------------------------------------------------
// Problem constants
// ---------------------------------------------------------------------------
#define N_TOK   65536
#define C_CODES 2048
#define D       64
#define KEXT    144                  // [ah|ah|1,1,pad] x [eh|el|e2h,e2l,pad]
#define M_TILE  128
#define N_TILE  64                   // codes per chunk
#define NCHUNK  (C_CODES / N_TILE)   // 32
#define MARGIN  0.15f
#define NTHR    256

#define DECAY_F 0.8f
#define OMD_F   0.2f
#define EPS_F   1e-5f

// smem row stride 304 B (76 words ≡ 12 mod 32 -> ldmatrix conflict-free)
#define RSTRIDE      304
#define A_BYTES      (M_TILE * RSTRIDE)      // 38912
#define BCH_BYTES    (N_TILE * RSTRIDE)      // 19456
#define SMEM_B_OFF   A_BYTES
#define SMEM_DYN     (A_BYTES + 2 * BCH_BYTES)   // 77824 -> 2 CTAs/SM

// k_exact smem
#define EX_RS        68
#define EX_SMEM      (256*EX_RS*4 + 32*64*4 + 256*4 + 128)  // 78976

// Output layout (floats), reference return order
#define OFF_Q    0
#define OFF_IND  4194304
#define OFF_NE   4259840
#define OFF_NCS  4390912
#define OFF_NEA  4392960

// ---------------------------------------------------------------------------
// Device scratch
// ---------------------------------------------------------------------------
__device__ __nv_bfloat16 g_B[(size_t)C_CODES * KEXT];
__device__ float g_e2[C_CODES];
__device__ int   g_ind[N_TOK];
__device__ float g_counts[C_CODES];
__device__ float g_sum[C_CODES * D];
__device__ int   g_namb;
__device__ int   g_amb[N_TOK];
__device__ unsigned long long g_bestpack[N_TOK];

// ---------------------------------------------------------------------------
// PTX helpers (baseline sm_80-era only — safe on plain sm_103 target)
// ---------------------------------------------------------------------------
__device__ __forceinline__ uint32_t smem_u32(const void* p) {
    return (uint32_t)__cvta_generic_to_shared(p);
}
__device__ __forceinline__ void cp16(uint32_t saddr, const void* g) {
    asm volatile("cp.async.cg.shared.global [%0], [%1], 16;" :: "r"(saddr), "l"(g));
}
__device__ __forceinline__ void cp_commit() {
    asm volatile("cp.async.commit_group;" ::: "memory");
}
template <int NN> __device__ __forceinline__ void cp_wait() {
    asm volatile("cp.async.wait_group %0;" :: "n"(NN) : "memory");
}
__device__ __forceinline__ void ldsm4(uint32_t* r, uint32_t addr) {
    asm volatile("ldmatrix.sync.aligned.m8n8.x4.shared.b16 {%0,%1,%2,%3}, [%4];"
                 : "=r"(r[0]), "=r"(r[1]), "=r"(r[2]), "=r"(r[3]) : "r"(addr));
}
__device__ __forceinline__ void mma16816(float* d, const uint32_t* a,
                                         uint32_t b0, uint32_t b1) {
    asm volatile(
        "mma.sync.aligned.m16n8k16.row.col.f32.bf16.bf16.f32 "
        "{%0,%1,%2,%3}, {%4,%5,%6,%7}, {%8,%9}, {%0,%1,%2,%3};"
        : "+f"(d[0]), "+f"(d[1]), "+f"(d[2]), "+f"(d[3])
        : "r"(a[0]), "r"(a[1]), "r"(a[2]), "r"(a[3]), "r"(b0), "r"(b1));
}

// ---------------------------------------------------------------------------
// k_zero
// ---------------------------------------------------------------------------
__global__ void k_zero() {
    int i = blockIdx.x * blockDim.x + threadIdx.x;
    if (i == 0) g_namb = 0;
    if (i < C_CODES) g_counts[i] = 0.0f;
    if (i < C_CODES * D) g_sum[i] = 0.0f;
    if (i < N_TOK) g_bestpack[i] = 0xFFFFFFFFFFFFFFFFull;
}

// ---------------------------------------------------------------------------
// k_prep_b: B row = [eh | el | e2h,e2l, 0...] bf16; e2 fp32 for k_exact.
// ---------------------------------------------------------------------------
__global__ void k_prep_b(const float* __restrict__ emb) {
    int c = (blockIdx.x * blockDim.x + threadIdx.x) >> 5;
    int lane = threadIdx.x & 31;
    if (c >= C_CODES) return;
    float2 v = *(const float2*)(emb + (size_t)c * D + lane * 2);
    __nv_bfloat16 h0 = __float2bfloat16(v.x), h1 = __float2bfloat16(v.y);
    __nv_bfloat16 l0 = __float2bfloat16(v.x - __bfloat162float(h0));
    __nv_bfloat16 l1 = __float2bfloat16(v.y - __bfloat162float(h1));
    float sq = v.x * v.x + v.y * v.y;
    #pragma unroll
    for (int m = 16; m >= 1; m >>= 1)
        sq += __shfl_xor_sync(0xFFFFFFFFu, sq, m);
    __nv_bfloat162 hh; hh.x = h0; hh.y = h1;
    __nv_bfloat162 ll; ll.x = l0; ll.y = l1;
    __nv_bfloat162* base = (__nv_bfloat162*)(g_B + (size_t)c * KEXT);
    base[lane] = hh; base[32 + lane] = ll;
    if (lane == 0) {
        __nv_bfloat16 s2h = __float2bfloat16(sq);
        __nv_bfloat16 s2l = __float2bfloat16(sq - __bfloat162float(s2h));
        __nv_bfloat162 z; z.x = __float2bfloat16(0.f); z.y = z.x;
        __nv_bfloat162 e2p; e2p.x = s2h; e2p.y = s2l;
        base[64] = e2p;
        #pragma unroll
        for (int q = 65; q < 72; q++) base[q] = z;
        g_e2[c] = sq;
    }
}

// ---------------------------------------------------------------------------
// k_mma: HMMA split-GEMM (K=144) + fused argmin + fused scatter.
// A frags hoisted to registers (A is chunk-invariant; ks 4-7 == ks 0-3;
// tail A frag is an analytic constant). Per-chunk LDSM = B only (18).
// ---------------------------------------------------------------------------
__device__ __forceinline__ void issue_b(uint32_t dst, const __nv_bfloat16* src,
                                        int tid) {
    // 64 rows x 18 float4 (288 valid bytes of 304 row)
    #pragma unroll
    for (int it = 0; it < 5; it++) {
        int i = tid + it * NTHR;
        if (i < 64 * 18) {
            int n = i / 18, q = i - n * 18;
            cp16(dst + n * RSTRIDE + q * 16, src + (size_t)n * KEXT + q * 8);
        }
    }
}

extern __shared__ char smraw[];

__global__ __launch_bounds__(NTHR, 2) void k_mma(const float* __restrict__ x,
                                                 const float* __restrict__ emb,
                                                 float* __restrict__ out) {
    uint32_t A_s = smem_u32(smraw);
    uint32_t B_s = A_s + SMEM_B_OFF;

    __shared__ float s_bst[2][M_TILE];
    __shared__ float s_b2 [2][M_TILE];
    __shared__ int   s_bi [2][M_TILE];
    __shared__ int   s_fi [M_TILE];

    int tid = threadIdx.x;
    int lane = tid & 31, wid = tid >> 5;
    int warp_m = wid >> 1, warp_n = wid & 1;
    int g   = lane >> 2;
    int tig = lane & 3;
    int row0 = blockIdx.x * M_TILE;

    // prologue: B chunk 0
    issue_b(B_s, g_B, tid);
    cp_commit();

    // build A tile: [ah | ah], 128 rows (tail cols never touched by ldsm)
    {
        const float2* xsrc = (const float2*)(x + (size_t)row0 * D);
        for (int idx = tid; idx < M_TILE * 32; idx += NTHR) {
            int r = idx >> 5, c2 = idx & 31;
            float2 v = xsrc[r * 32 + c2];
            __nv_bfloat16 h0 = __float2bfloat16(-2.0f * v.x);
            __nv_bfloat16 h1 = __float2bfloat16(-2.0f * v.y);
            __nv_bfloat162 hh; hh.x = h0; hh.y = h1;
            __nv_bfloat162* rowp = (__nv_bfloat162*)(smraw + r * RSTRIDE);
            rowp[c2] = hh; rowp[32 + c2] = hh;
        }
    }
    __syncthreads();

    int lrow = lane & 15, lsel = lane >> 4;
    uint32_t a_addr0 = A_s + (uint32_t)(warp_m * 32 + lrow) * RSTRIDE + lsel * 16;
    uint32_t a_addr1 = a_addr0 + 16 * RSTRIDE;
    uint32_t b_off0  = (uint32_t)(warp_n * 32 + lrow) * RSTRIDE + lsel * 16;
    uint32_t b_off1  = b_off0 + 16 * RSTRIDE;

    // Hoisted A fragments: chunk-invariant, ks 0..3 (ks 4..7 identical).
    uint32_t Afr[2][4][4];
    #pragma unroll
    for (int ks = 0; ks < 4; ks++) {
        ldsm4(Afr[0][ks], a_addr0 + ks * 32);
        ldsm4(Afr[1][ks], a_addr1 + ks * 32);
    }
    // Tail A frag for cols [1,1,0...]: analytic constant, no smem.
    uint32_t at = (tig == 0) ? 0x3F803F80u : 0u;
    uint32_t Atail[4] = {at, at, 0u, 0u};

    float best[4], b2[4]; int bidx[4];
    #pragma unroll
    for (int i = 0; i < 4; i++) { best[i] = 3.4e38f; b2[i] = 3.4e38f; bidx[i] = 0; }

    for (int ch = 0; ch < NCHUNK; ch++) {
        cp_wait<0>();
        __syncthreads();
        if (ch + 1 < NCHUNK) {
            issue_b(B_s + ((ch + 1) & 1) * BCH_BYTES,
                    g_B + (size_t)(ch + 1) * N_TILE * KEXT, tid);
            cp_commit();
        }

        uint32_t bb = B_s + (ch & 1) * BCH_BYTES;
        uint32_t pb0 = bb + b_off0, pb1 = bb + b_off1;

        float acc[2][4][4];
        #pragma unroll
        for (int mt = 0; mt < 2; mt++)
            #pragma unroll
            for (int nt = 0; nt < 4; nt++)
                #pragma unroll
                for (int q = 0; q < 4; q++) acc[mt][nt][q] = 0.0f;

        #pragma unroll
        for (int ks = 0; ks < 4; ks++) {
            uint32_t Ba0[4], Ba1[4], Bb0[4], Bb1[4];
            ldsm4(Ba0, pb0 + ks * 32);
            ldsm4(Ba1, pb1 + ks * 32);
            ldsm4(Bb0, pb0 + (ks + 4) * 32);
            ldsm4(Bb1, pb1 + (ks + 4) * 32);
            #pragma unroll
            for (int mt = 0; mt < 2; mt++) {
                mma16816(acc[mt][0], Afr[mt][ks], Ba0[0], Ba0[2]);
                mma16816(acc[mt][1], Afr[mt][ks], Ba0[1], Ba0[3]);
                mma16816(acc[mt][2], Afr[mt][ks], Ba1[0], Ba1[2]);
                mma16816(acc[mt][3], Afr[mt][ks], Ba1[1], Ba1[3]);
                mma16816(acc[mt][0], Afr[mt][ks], Bb0[0], Bb0[2]);
                mma16816(acc[mt][1], Afr[mt][ks], Bb0[1], Bb0[3]);
                mma16816(acc[mt][2], Afr[mt][ks], Bb1[0], Bb1[2]);
                mma16816(acc[mt][3], Afr[mt][ks], Bb1[1], Bb1[3]);
            }
        }
        {   // tail k-step: e2 fold via constant A frag
            uint32_t Bt0[4], Bt1[4];
            ldsm4(Bt0, pb0 + 8 * 32);
            ldsm4(Bt1, pb1 + 8 * 32);
            #pragma unroll
            for (int mt = 0; mt < 2; mt++) {
                mma16816(acc[mt][0], Atail, Bt0[0], Bt0[2]);
                mma16816(acc[mt][1], Atail, Bt0[1], Bt0[3]);
                mma16816(acc[mt][2], Atail, Bt1[0], Bt1[2]);
                mma16816(acc[mt][3], Atail, Bt1[1], Bt1[3]);
            }
        }

        // branchless epilogue: 3-bit local idx in mantissa LSBs,
        // per-row-stream (m1, m2) via min/max chains, one unpack per chunk.
        #pragma unroll
        for (int mt = 0; mt < 2; mt++)
            #pragma unroll
            for (int e = 0; e < 2; e++) {
                int ri = mt * 2 + e;
                float m1 = 3.4e38f, m2 = 3.4e38f;
                #pragma unroll
                for (int nt = 0; nt < 4; nt++)
                    #pragma unroll
                    for (int b = 0; b < 2; b++) {
                        float s = acc[mt][nt][e * 2 + b];
                        uint32_t u = (__float_as_uint(s) & ~7u) |
                                     (uint32_t)(nt * 2 + b);
                        float sp = __uint_as_float(u);
                        m2 = fminf(m2, fmaxf(m1, sp));
                        m1 = fminf(m1, sp);
                    }
                uint32_t lu = __float_as_uint(m1) & 7u;
                int code = ch * N_TILE + warp_n * 32 +
                           (int)(lu >> 1) * 8 + tig * 2 + (int)(lu & 1);
                float hb = fmaxf(best[ri], m1);
                b2[ri] = fminf(fminf(b2[ri], m2), hb);
                if (m1 < best[ri]) { best[ri] = m1; bidx[ri] = code; }
            }
    }

    // quad reduce (4 tig lanes share each row)
    #pragma unroll
    for (int ri = 0; ri < 4; ri++) {
        float s = best[ri], t = b2[ri]; int i = bidx[ri];
        #pragma unroll
        for (int m = 1; m <= 2; m <<= 1) {
            float so = __shfl_xor_sync(0xFFFFFFFFu, s, m);
            float to = __shfl_xor_sync(0xFFFFFFFFu, t, m);
            int   io = __shfl_xor_sync(0xFFFFFFFFu, i, m);
            float hb  = fmaxf(s, so);
            float nb2 = fminf(fminf(t, to), hb);
            if (so < s || (so == s && io < i)) { s = so; i = io; }
            t = nb2;
        }
        best[ri] = s; b2[ri] = t; bidx[ri] = i;
    }
    if (tig == 0) {
        #pragma unroll
        for (int ri = 0; ri < 4; ri++) {
            int row = warp_m * 32 + (ri >> 1) * 16 + (ri & 1) * 8 + g;
            s_bst[warp_n][row] = best[ri];
            s_b2 [warp_n][row] = b2[ri];
            s_bi [warp_n][row] = bidx[ri];
        }
    }
    __syncthreads();

    if (tid < M_TILE) {
        float sA = s_bst[0][tid], sB = s_bst[1][tid];
        float tA = s_b2[0][tid],  tB = s_b2[1][tid];
        int   iA = s_bi[0][tid],  iB = s_bi[1][tid];
        float hb  = fmaxf(sA, sB);
        float fb2 = fminf(fminf(tA, tB), hb);
        float fb; int fi;
        if (sB < sA || (sB == sA && iB < iA)) { fb = sB; fi = iB; }
        else                                  { fb = sA; fi = iA; }
        s_fi[tid] = fi;
        g_ind[row0 + tid] = fi;
        out[OFF_IND + row0 + tid] = (float)fi;
        atomicAdd(g_counts + fi, 1.0f);
        if (fb2 - fb <= MARGIN) {
            int sl = atomicAdd(&g_namb, 1);
            g_amb[sl] = row0 + tid;
        }
    }
    __syncthreads();

    // fused scatter: warp per row — gather quantize, scatter feature sums
    for (int r = wid; r < M_TILE; r += 8) {
        int idx = s_fi[r];
        float2 q = *(const float2*)(emb + (size_t)idx * D + lane * 2);
        *(float2*)(out + OFF_Q + (size_t)(row0 + r) * D + lane * 2) = q;
        float2 xv = *(const float2*)(x + (size_t)(row0 + r) * D + lane * 2);
        atomicAdd(g_sum + (size_t)idx * D + lane * 2,     xv.x);
        atomicAdd(g_sum + (size_t)idx * D + lane * 2 + 1, xv.y);
    }
}

// ---------------------------------------------------------------------------
// k_exact: exact fp32 argmin for ambiguous rows. Task = 32 rows x 256 codes.
// Register-blocked 4 rows x 8 codes per thread: e-vectors reused across 4
// rows (2.75x less smem traffic than 1x32). atomicMin(u64) merge.
// ---------------------------------------------------------------------------
__global__ __launch_bounds__(256, 2) void k_exact(const float* __restrict__ x,
                                                  const float* __restrict__ emb) {
    extern __shared__ float esm[];
    float* s_e  = esm;                       // 256 x EX_RS
    float* s_x  = esm + 256 * EX_RS;         // 32 x 64
    float* s_e2 = s_x + 32 * 64;             // 256
    int*   s_rid = (int*)(s_e2 + 256);       // 32

    int nn = g_namb;
    int ntasks = ((nn + 31) >> 5) * 8;
    int tid = threadIdx.x;

    for (int task = blockIdx.x; task < ntasks; task += gridDim.x) {
        int rg = task >> 3, cc = task & 7;
        __syncthreads();
        if (tid < 32) {
            int ai = rg * 32 + tid;
            s_rid[tid] = (ai < nn) ? g_amb[ai] : -1;
        }
        for (int i = tid; i < 256 * 16; i += 256) {
            int c = i >> 4, q = i & 15;
            float4 v = *(const float4*)(emb + ((size_t)(cc * 256 + c)) * 64 + q * 4);
            *(float4*)(s_e + c * EX_RS + q * 4) = v;
        }
        s_e2[tid] = g_e2[cc * 256 + tid];
        __syncthreads();
        for (int i = tid; i < 32 * 16; i += 256) {
            int r = i >> 4, q = i & 15;
            int rid = s_rid[r];
            float4 v = (rid >= 0)
                ? *(const float4*)(x + (size_t)rid * 64 + q * 4)
                : make_float4(0.f, 0.f, 0.f, 0.f);
            *(float4*)(s_x + r * 64 + q * 4) = v;
        }
        __syncthreads();

        int rb = tid >> 5;        // 0..7: block of 4 rows
        int cb = tid & 31;        // 0..31: 8 codes, stride-32 interleave

        float dots[4][8];
        #pragma unroll
        for (int r = 0; r < 4; r++)
            #pragma unroll
            for (int j = 0; j < 8; j++) dots[r][j] = 0.f;

        #pragma unroll
        for (int kt = 0; kt < 8; kt++) {        // 8 floats per step
            float4 xv[4][2];
            #pragma unroll
            for (int r = 0; r < 4; r++) {
                xv[r][0] = *(const float4*)(s_x + (rb * 4 + r) * 64 + kt * 8);
                xv[r][1] = *(const float4*)(s_x + (rb * 4 + r) * 64 + kt * 8 + 4);
            }
            #pragma unroll
            for (int j = 0; j < 8; j++) {
                int c = cb + 32 * j;
                float4 e0 = *(const float4*)(s_e + c * EX_RS + kt * 8);
                float4 e1 = *(const float4*)(s_e + c * EX_RS + kt * 8 + 4);
                #pragma unroll
                for (int r = 0; r < 4; r++) {
                    dots[r][j] += xv[r][0].x * e0.x + xv[r][0].y * e0.y +
                                  xv[r][0].z * e0.z + xv[r][0].w * e0.w +
                                  xv[r][1].x * e1.x + xv[r][1].y * e1.y +
                                  xv[r][1].z * e1.z + xv[r][1].w * e1.w;
                }
            }
        }

        #pragma unroll
        for (int r = 0; r < 4; r++) {
            int rid = s_rid[rb * 4 + r];
            if (rid < 0) continue;
            float best = 3.4e38f; int bi = 0x7FFFFFFF;
            #pragma unroll
            for (int j = 0; j < 8; j++) {
                int c = cb + 32 * j;
                float sc = s_e2[c] - 2.0f * dots[r][j];
                int gc = cc * 256 + c;
                if (sc < best || (sc == best && gc < bi)) { best = sc; bi = gc; }
            }
            uint32_t u = __float_as_uint(best);
            u ^= (u & 0x80000000u) ? 0xFFFFFFFFu : 0x80000000u;
            unsigned long long pk =
                ((unsigned long long)u << 32) | (unsigned)bi;
            atomicMin(&g_bestpack[rid], pk);
        }
    }
}

// ---------------------------------------------------------------------------
// k_fix: patch rows where exact argmin differs from the approx one used by
// the fused scatter — rewrite ind/quantize, compensate count/sum atomics.
// ---------------------------------------------------------------------------
__global__ void k_fix(const float* __restrict__ x,
                      const float* __restrict__ emb,
                      float* __restrict__ out) {
    int nn = g_namb;
    int w = (blockIdx.x * blockDim.x + threadIdx.x) >> 5;
    int lane = threadIdx.x & 31;
    int nw = (gridDim.x * blockDim.x) >> 5;
    for (int i = w; i < nn; i += nw) {
        int row = g_amb[i];
        int newi = (int)(g_bestpack[row] & 0xFFFFFFFFull);
        int oldi = g_ind[row];
        if (newi == oldi) continue;
        if (lane == 0) {
            g_ind[row] = newi;
            out[OFF_IND + row] = (float)newi;
            atomicAdd(g_counts + oldi, -1.0f);
            atomicAdd(g_counts + newi,  1.0f);
        }
        float2 q = *(const float2*)(emb + (size_t)newi * D + lane * 2);
        *(float2*)(out + OFF_Q + (size_t)row * D + lane * 2) = q;
        float2 xv = *(const float2*)(x + (size_t)row * D + lane * 2);
        atomicAdd(g_sum + (size_t)oldi * D + lane * 2,     -xv.x);
        atomicAdd(g_sum + (size_t)oldi * D + lane * 2 + 1, -xv.y);
        atomicAdd(g_sum + (size_t)newi * D + lane * 2,      xv.x);
        atomicAdd(g_sum + (size_t)newi * D + lane * 2 + 1,  xv.y);
    }
}

// ---------------------------------------------------------------------------
// k_final: EMA + laplace smoothing + renormalize.
// ---------------------------------------------------------------------------
__global__ __launch_bounds__(1024)
void k_final(const float* __restrict__ cs,
             const float* __restrict__ ea,
             float* __restrict__ out) {
    __shared__ float s_ncs[C_CODES];
    __shared__ float s_red[32];
    int tid = threadIdx.x;

    float local = 0.0f;
    for (int c = tid; c < C_CODES; c += 1024) {
        float v = cs[c] * DECAY_F + g_counts[c] * OMD_F;
        s_ncs[c] = v;
        out[OFF_NCS + c] = v;
        local += v;
    }
    #pragma unroll
    for (int m = 16; m >= 1; m >>= 1)
        local += __shfl_xor_sync(0xFFFFFFFFu, local, m);
    if ((tid & 31) == 0) s_red[tid >> 5] = local;
    __syncthreads();
    if (tid < 32) {
        float v = s_red[tid];
        #pragma unroll
        for (int m = 16; m >= 1; m >>= 1)
            v += __shfl_xor_sync(0xFFFFFFFFu, v, m);
        if (tid == 0) s_red[0] = v;
    }
    __syncthreads();
    float tot   = s_red[0];
    float denom = tot + (float)C_CODES * EPS_F;

    for (int i = tid; i < C_CODES * D; i += 1024) {
        int c = i >> 6;
        float nea = ea[i] * DECAY_F + g_sum[i] * OMD_F;
        out[OFF_NEA + i] = nea;
        float sm = (s_ncs[c] + EPS_F) / denom * tot;
        out[OFF_NE + i] = nea / sm;
    }
}

// ---------------------------------------------------------------------------
// kernel_launch
// ---------------------------------------------------------------------------
extern "C" void kernel_launch(void* const* d_in, const int* in_sizes, int n_in,
                              void* d_out, int out_size) {
    (void)in_sizes; (void)n_in; (void)out_size;
    const float* x   = (const float*)d_in[0];
    const float* emb = (const float*)d_in[1];
    const float* cs  = (const float*)d_in[2];
    const float* ea  = (const float*)d_in[3];
    float* out = (float*)d_out;

    cudaFuncSetAttribute(k_mma, cudaFuncAttributeMaxDynamicSharedMemorySize,
                         SMEM_DYN);
    cudaFuncSetAttribute(k_exact, cudaFuncAttributeMaxDynamicSharedMemorySize,
                         EX_SMEM);

    k_zero<<<512, 256>>>();
    k_prep_b<<<256, 256>>>(emb);
    k_mma<<<N_TOK / M_TILE, NTHR, SMEM_DYN>>>(x, emb, out);
    k_exact<<<1024, 256, EX_SMEM>>>(x, emb);
    k_fix<<<64, 256>>>(x, emb, out);
    k_final<<<1, 1024>>>(cs, ea, out);
}

// round 15
// speedup vs baseline: 1.4829x; 1.1457x over previous
#include <cuda_runtime.h>
#include <cuda_bf16.h>
#include <cstdint>

// ---------------------------------------------------------------------------
// Problem constants
// ---------------------------------------------------------------------------
#define N_TOK   65536
#define C_CODES 2048
#define D       64
#define KEXT    80                   // [ah|1,1,pad] x [eh|e2h,e2l,pad]
#define M_TILE  128
#define N_TILE  64                   // codes per chunk
#define NCHUNK  (C_CODES / N_TILE)   // 32
#define MARGIN  0.22f
#define NTHR    256

#define DECAY_F 0.8f
#define OMD_F   0.2f
#define EPS_F   1e-5f

// smem row stride 176 B (11 16B-units ≡ 3 mod 8 -> ldmatrix conflict-free)
#define RSTRIDE      176
#define A_BYTES      (M_TILE * RSTRIDE)      // 22528
#define BCH_BYTES    (N_TILE * RSTRIDE)      // 11264
#define SMEM_B_OFF   A_BYTES
#define SMEM_DYN     (A_BYTES + 2 * BCH_BYTES)   // 45056 -> 2 CTAs/SM

// k_exact smem
#define EX_RS        68
#define EX_SMEM      (256*EX_RS*4 + 32*64*4 + 256*4 + 128)  // 78976

// Output layout (floats), reference return order
#define OFF_Q    0
#define OFF_IND  4194304
#define OFF_NE   4259840
#define OFF_NCS  4390912
#define OFF_NEA  4392960

// ---------------------------------------------------------------------------
// Device scratch
// ---------------------------------------------------------------------------
__device__ __nv_bfloat16 g_B[(size_t)C_CODES * KEXT];
__device__ float g_e2[C_CODES];
__device__ int   g_ind[N_TOK];
__device__ float g_counts[C_CODES];
__device__ float g_sum[C_CODES * D];
__device__ int   g_namb;
__device__ int   g_amb[N_TOK];
__device__ unsigned long long g_bestpack[N_TOK];

// ---------------------------------------------------------------------------
// PTX helpers (baseline sm_80-era only — safe on plain sm_103 target)
// ---------------------------------------------------------------------------
__device__ __forceinline__ uint32_t smem_u32(const void* p) {
    return (uint32_t)__cvta_generic_to_shared(p);
}
__device__ __forceinline__ void cp16(uint32_t saddr, const void* g) {
    asm volatile("cp.async.cg.shared.global [%0], [%1], 16;" :: "r"(saddr), "l"(g));
}
__device__ __forceinline__ void cp_commit() {
    asm volatile("cp.async.commit_group;" ::: "memory");
}
template <int NN> __device__ __forceinline__ void cp_wait() {
    asm volatile("cp.async.wait_group %0;" :: "n"(NN) : "memory");
}
__device__ __forceinline__ void ldsm4(uint32_t* r, uint32_t addr) {
    asm volatile("ldmatrix.sync.aligned.m8n8.x4.shared.b16 {%0,%1,%2,%3}, [%4];"
                 : "=r"(r[0]), "=r"(r[1]), "=r"(r[2]), "=r"(r[3]) : "r"(addr));
}
__device__ __forceinline__ void mma16816(float* d, const uint32_t* a,
                                         uint32_t b0, uint32_t b1) {
    asm volatile(
        "mma.sync.aligned.m16n8k16.row.col.f32.bf16.bf16.f32 "
        "{%0,%1,%2,%3}, {%4,%5,%6,%7}, {%8,%9}, {%0,%1,%2,%3};"
        : "+f"(d[0]), "+f"(d[1]), "+f"(d[2]), "+f"(d[3])
        : "r"(a[0]), "r"(a[1]), "r"(a[2]), "r"(a[3]), "r"(b0), "r"(b1));
}

// ---------------------------------------------------------------------------
// k_zero
// ---------------------------------------------------------------------------
__global__ void k_zero() {
    int i = blockIdx.x * blockDim.x + threadIdx.x;
    if (i == 0) g_namb = 0;
    if (i < C_CODES) g_counts[i] = 0.0f;
    if (i < C_CODES * D) g_sum[i] = 0.0f;
    if (i < N_TOK) g_bestpack[i] = 0xFFFFFFFFFFFFFFFFull;
}

// ---------------------------------------------------------------------------
// k_prep_b: B row = [eh(64) | e2h,e2l, 0...] bf16; e2 fp32 for k_exact.
// ---------------------------------------------------------------------------
__global__ void k_prep_b(const float* __restrict__ emb) {
    int c = (blockIdx.x * blockDim.x + threadIdx.x) >> 5;
    int lane = threadIdx.x & 31;
    if (c >= C_CODES) return;
    float2 v = *(const float2*)(emb + (size_t)c * D + lane * 2);
    __nv_bfloat16 h0 = __float2bfloat16(v.x), h1 = __float2bfloat16(v.y);
    float sq = v.x * v.x + v.y * v.y;
    #pragma unroll
    for (int m = 16; m >= 1; m >>= 1)
        sq += __shfl_xor_sync(0xFFFFFFFFu, sq, m);
    __nv_bfloat162 hh; hh.x = h0; hh.y = h1;
    __nv_bfloat162* base = (__nv_bfloat162*)(g_B + (size_t)c * KEXT);
    base[lane] = hh;
    if (lane == 0) {
        __nv_bfloat16 s2h = __float2bfloat16(sq);
        __nv_bfloat16 s2l = __float2bfloat16(sq - __bfloat162float(s2h));
        __nv_bfloat162 z; z.x = __float2bfloat16(0.f); z.y = z.x;
        __nv_bfloat162 e2p; e2p.x = s2h; e2p.y = s2l;
        base[32] = e2p;
        #pragma unroll
        for (int q = 33; q < 40; q++) base[q] = z;
        g_e2[c] = sq;
    }
}

// ---------------------------------------------------------------------------
// k_mma: HMMA GEMM (K=80: ah·eh + e2 tail) + fused argmin + fused scatter.
// A frags hoisted to registers (chunk-invariant); tail A frag analytic.
// Per-chunk LDSM = B only (10). CTA = 256 thr (8 warps, 4m x 2n), 2 CTAs/SM.
// ---------------------------------------------------------------------------
__device__ __forceinline__ void issue_b(uint32_t dst, const __nv_bfloat16* src,
                                        int tid) {
    // 64 rows x 10 float4 (160 valid bytes of 176 row)
    #pragma unroll
    for (int it = 0; it < 3; it++) {
        int i = tid + it * NTHR;
        if (i < 64 * 10) {
            int n = i / 10, q = i - n * 10;
            cp16(dst + n * RSTRIDE + q * 16, src + (size_t)n * KEXT + q * 8);
        }
    }
}

extern __shared__ char smraw[];

__global__ __launch_bounds__(NTHR, 2) void k_mma(const float* __restrict__ x,
                                                 const float* __restrict__ emb,
                                                 float* __restrict__ out) {
    uint32_t A_s = smem_u32(smraw);
    uint32_t B_s = A_s + SMEM_B_OFF;

    __shared__ float s_bst[2][M_TILE];
    __shared__ float s_b2 [2][M_TILE];
    __shared__ int   s_bi [2][M_TILE];
    __shared__ int   s_fi [M_TILE];

    int tid = threadIdx.x;
    int lane = tid & 31, wid = tid >> 5;
    int warp_m = wid >> 1, warp_n = wid & 1;
    int g   = lane >> 2;
    int tig = lane & 3;
    int row0 = blockIdx.x * M_TILE;

    // prologue: B chunk 0
    issue_b(B_s, g_B, tid);
    cp_commit();

    // build A tile: [ah(64)], 128 rows (tail cols never touched by ldsm)
    {
        const float2* xsrc = (const float2*)(x + (size_t)row0 * D);
        for (int idx = tid; idx < M_TILE * 32; idx += NTHR) {
            int r = idx >> 5, c2 = idx & 31;
            float2 v = xsrc[r * 32 + c2];
            __nv_bfloat16 h0 = __float2bfloat16(-2.0f * v.x);
            __nv_bfloat16 h1 = __float2bfloat16(-2.0f * v.y);
            __nv_bfloat162 hh; hh.x = h0; hh.y = h1;
            ((__nv_bfloat162*)(smraw + r * RSTRIDE))[c2] = hh;
        }
    }
    __syncthreads();

    int lrow = lane & 15, lsel = lane >> 4;
    uint32_t a_addr0 = A_s + (uint32_t)(warp_m * 32 + lrow) * RSTRIDE + lsel * 16;
    uint32_t a_addr1 = a_addr0 + 16 * RSTRIDE;
    uint32_t b_off0  = (uint32_t)(warp_n * 32 + lrow) * RSTRIDE + lsel * 16;
    uint32_t b_off1  = b_off0 + 16 * RSTRIDE;

    // Hoisted A fragments: chunk-invariant, ks 0..3 (cols 0..63).
    uint32_t Afr[2][4][4];
    #pragma unroll
    for (int ks = 0; ks < 4; ks++) {
        ldsm4(Afr[0][ks], a_addr0 + ks * 32);
        ldsm4(Afr[1][ks], a_addr1 + ks * 32);
    }
    // Tail A frag for cols [1,1,0...]: analytic constant, no smem.
    uint32_t at = (tig == 0) ? 0x3F803F80u : 0u;
    uint32_t Atail[4] = {at, at, 0u, 0u};

    float best[4], b2[4]; int bidx[4];
    #pragma unroll
    for (int i = 0; i < 4; i++) { best[i] = 3.4e38f; b2[i] = 3.4e38f; bidx[i] = 0; }

    for (int ch = 0; ch < NCHUNK; ch++) {
        cp_wait<0>();
        __syncthreads();
        if (ch + 1 < NCHUNK) {
            issue_b(B_s + ((ch + 1) & 1) * BCH_BYTES,
                    g_B + (size_t)(ch + 1) * N_TILE * KEXT, tid);
            cp_commit();
        }

        uint32_t bb = B_s + (ch & 1) * BCH_BYTES;
        uint32_t pb0 = bb + b_off0, pb1 = bb + b_off1;

        float acc[2][4][4];
        #pragma unroll
        for (int mt = 0; mt < 2; mt++)
            #pragma unroll
            for (int nt = 0; nt < 4; nt++)
                #pragma unroll
                for (int q = 0; q < 4; q++) acc[mt][nt][q] = 0.0f;

        #pragma unroll
        for (int ks = 0; ks < 4; ks++) {
            uint32_t B0[4], B1[4];
            ldsm4(B0, pb0 + ks * 32);
            ldsm4(B1, pb1 + ks * 32);
            #pragma unroll
            for (int mt = 0; mt < 2; mt++) {
                mma16816(acc[mt][0], Afr[mt][ks], B0[0], B0[2]);
                mma16816(acc[mt][1], Afr[mt][ks], B0[1], B0[3]);
                mma16816(acc[mt][2], Afr[mt][ks], B1[0], B1[2]);
                mma16816(acc[mt][3], Afr[mt][ks], B1[1], B1[3]);
            }
        }
        {   // tail k-step: e2 fold via constant A frag (B cols 64..79)
            uint32_t Bt0[4], Bt1[4];
            ldsm4(Bt0, pb0 + 4 * 32);
            ldsm4(Bt1, pb1 + 4 * 32);
            #pragma unroll
            for (int mt = 0; mt < 2; mt++) {
                mma16816(acc[mt][0], Atail, Bt0[0], Bt0[2]);
                mma16816(acc[mt][1], Atail, Bt0[1], Bt0[3]);
                mma16816(acc[mt][2], Atail, Bt1[0], Bt1[2]);
                mma16816(acc[mt][3], Atail, Bt1[1], Bt1[3]);
            }
        }

        // branchless epilogue: 3-bit local idx in mantissa LSBs,
        // per-row-stream (m1, m2) via min/max chains, one unpack per chunk.
        #pragma unroll
        for (int mt = 0; mt < 2; mt++)
            #pragma unroll
            for (int e = 0; e < 2; e++) {
                int ri = mt * 2 + e;
                float m1 = 3.4e38f, m2 = 3.4e38f;
                #pragma unroll
                for (int nt = 0; nt < 4; nt++)
                    #pragma unroll
                    for (int b = 0; b < 2; b++) {
                        float s = acc[mt][nt][e * 2 + b];
                        uint32_t u = (__float_as_uint(s) & ~7u) |
                                     (uint32_t)(nt * 2 + b);
                        float sp = __uint_as_float(u);
                        m2 = fminf(m2, fmaxf(m1, sp));
                        m1 = fminf(m1, sp);
                    }
                uint32_t lu = __float_as_uint(m1) & 7u;
                int code = ch * N_TILE + warp_n * 32 +
                           (int)(lu >> 1) * 8 + tig * 2 + (int)(lu & 1);
                float hb = fmaxf(best[ri], m1);
                b2[ri] = fminf(fminf(b2[ri], m2), hb);
                if (m1 < best[ri]) { best[ri] = m1; bidx[ri] = code; }
            }
    }

    // quad reduce (4 tig lanes share each row)
    #pragma unroll
    for (int ri = 0; ri < 4; ri++) {
        float s = best[ri], t = b2[ri]; int i = bidx[ri];
        #pragma unroll
        for (int m = 1; m <= 2; m <<= 1) {
            float so = __shfl_xor_sync(0xFFFFFFFFu, s, m);
            float to = __shfl_xor_sync(0xFFFFFFFFu, t, m);
            int   io = __shfl_xor_sync(0xFFFFFFFFu, i, m);
            float hb  = fmaxf(s, so);
            float nb2 = fminf(fminf(t, to), hb);
            if (so < s || (so == s && io < i)) { s = so; i = io; }
            t = nb2;
        }
        best[ri] = s; b2[ri] = t; bidx[ri] = i;
    }
    if (tig == 0) {
        #pragma unroll
        for (int ri = 0; ri < 4; ri++) {
            int row = warp_m * 32 + (ri >> 1) * 16 + (ri & 1) * 8 + g;
            s_bst[warp_n][row] = best[ri];
            s_b2 [warp_n][row] = b2[ri];
            s_bi [warp_n][row] = bidx[ri];
        }
    }
    __syncthreads();

    if (tid < M_TILE) {
        float sA = s_bst[0][tid], sB = s_bst[1][tid];
        float tA = s_b2[0][tid],  tB = s_b2[1][tid];
        int   iA = s_bi[0][tid],  iB = s_bi[1][tid];
        float hb  = fmaxf(sA, sB);
        float fb2 = fminf(fminf(tA, tB), hb);
        float fb; int fi;
        if (sB < sA || (sB == sA && iB < iA)) { fb = sB; fi = iB; }
        else                                  { fb = sA; fi = iA; }
        s_fi[tid] = fi;
        g_ind[row0 + tid] = fi;
        out[OFF_IND + row0 + tid] = (float)fi;
        atomicAdd(g_counts + fi, 1.0f);
        if (fb2 - fb <= MARGIN) {
            int sl = atomicAdd(&g_namb, 1);
            g_amb[sl] = row0 + tid;
        }
    }
    __syncthreads();

    // fused scatter: warp per row — gather quantize, scatter feature sums
    for (int r = wid; r < M_TILE; r += 8) {
        int idx = s_fi[r];
        float2 q = *(const float2*)(emb + (size_t)idx * D + lane * 2);
        *(float2*)(out + OFF_Q + (size_t)(row0 + r) * D + lane * 2) = q;
        float2 xv = *(const float2*)(x + (size_t)(row0 + r) * D + lane * 2);
        atomicAdd(g_sum + (size_t)idx * D + lane * 2,     xv.x);
        atomicAdd(g_sum + (size_t)idx * D + lane * 2 + 1, xv.y);
    }
}

// ---------------------------------------------------------------------------
// k_exact: exact fp32 argmin for ambiguous rows. Task = 32 rows x 256 codes.
// Register-blocked 4 rows x 8 codes per thread. atomicMin(u64) merge.
// ---------------------------------------------------------------------------
__global__ __launch_bounds__(256, 2) void k_exact(const float* __restrict__ x,
                                                  const float* __restrict__ emb) {
    extern __shared__ float esm[];
    float* s_e  = esm;                       // 256 x EX_RS
    float* s_x  = esm + 256 * EX_RS;         // 32 x 64
    float* s_e2 = s_x + 32 * 64;             // 256
    int*   s_rid = (int*)(s_e2 + 256);       // 32

    int nn = g_namb;
    int ntasks = ((nn + 31) >> 5) * 8;
    int tid = threadIdx.x;

    for (int task = blockIdx.x; task < ntasks; task += gridDim.x) {
        int rg = task >> 3, cc = task & 7;
        __syncthreads();
        if (tid < 32) {
            int ai = rg * 32 + tid;
            s_rid[tid] = (ai < nn) ? g_amb[ai] : -1;
        }
        for (int i = tid; i < 256 * 16; i += 256) {
            int c = i >> 4, q = i & 15;
            float4 v = *(const float4*)(emb + ((size_t)(cc * 256 + c)) * 64 + q * 4);
            *(float4*)(s_e + c * EX_RS + q * 4) = v;
        }
        s_e2[tid] = g_e2[cc * 256 + tid];
        __syncthreads();
        for (int i = tid; i < 32 * 16; i += 256) {
            int r = i >> 4, q = i & 15;
            int rid = s_rid[r];
            float4 v = (rid >= 0)
                ? *(const float4*)(x + (size_t)rid * 64 + q * 4)
                : make_float4(0.f, 0.f, 0.f, 0.f);
            *(float4*)(s_x + r * 64 + q * 4) = v;
        }
        __syncthreads();

        int rb = tid >> 5;        // 0..7: block of 4 rows
        int cb = tid & 31;        // 0..31: 8 codes, stride-32 interleave

        float dots[4][8];
        #pragma unroll
        for (int r = 0; r < 4; r++)
            #pragma unroll
            for (int j = 0; j < 8; j++) dots[r][j] = 0.f;

        #pragma unroll
        for (int kt = 0; kt < 8; kt++) {        // 8 floats per step
            float4 xv[4][2];
            #pragma unroll
            for (int r = 0; r < 4; r++) {
                xv[r][0] = *(const float4*)(s_x + (rb * 4 + r) * 64 + kt * 8);
                xv[r][1] = *(const float4*)(s_x + (rb * 4 + r) * 64 + kt * 8 + 4);
            }
            #pragma unroll
            for (int j = 0; j < 8; j++) {
                int c = cb + 32 * j;
                float4 e0 = *(const float4*)(s_e + c * EX_RS + kt * 8);
                float4 e1 = *(const float4*)(s_e + c * EX_RS + kt * 8 + 4);
                #pragma unroll
                for (int r = 0; r < 4; r++) {
                    dots[r][j] += xv[r][0].x * e0.x + xv[r][0].y * e0.y +
                                  xv[r][0].z * e0.z + xv[r][0].w * e0.w +
                                  xv[r][1].x * e1.x + xv[r][1].y * e1.y +
                                  xv[r][1].z * e1.z + xv[r][1].w * e1.w;
                }
            }
        }

        #pragma unroll
        for (int r = 0; r < 4; r++) {
            int rid = s_rid[rb * 4 + r];
            if (rid < 0) continue;
            float best = 3.4e38f; int bi = 0x7FFFFFFF;
            #pragma unroll
            for (int j = 0; j < 8; j++) {
                int c = cb + 32 * j;
                float sc = s_e2[c] - 2.0f * dots[r][j];
                int gc = cc * 256 + c;
                if (sc < best || (sc == best && gc < bi)) { best = sc; bi = gc; }
            }
            uint32_t u = __float_as_uint(best);
            u ^= (u & 0x80000000u) ? 0xFFFFFFFFu : 0x80000000u;
            unsigned long long pk =
                ((unsigned long long)u << 32) | (unsigned)bi;
            atomicMin(&g_bestpack[rid], pk);
        }
    }
}

// ---------------------------------------------------------------------------
// k_fix: patch rows where exact argmin differs from the approx one used by
// the fused scatter — rewrite ind/quantize, compensate count/sum atomics.
// ---------------------------------------------------------------------------
__global__ void k_fix(const float* __restrict__ x,
                      const float* __restrict__ emb,
                      float* __restrict__ out) {
    int nn = g_namb;
    int w = (blockIdx.x * blockDim.x + threadIdx.x) >> 5;
    int lane = threadIdx.x & 31;
    int nw = (gridDim.x * blockDim.x) >> 5;
    for (int i = w; i < nn; i += nw) {
        int row = g_amb[i];
        int newi = (int)(g_bestpack[row] & 0xFFFFFFFFull);
        int oldi = g_ind[row];
        if (newi == oldi) continue;
        if (lane == 0) {
            g_ind[row] = newi;
            out[OFF_IND + row] = (float)newi;
            atomicAdd(g_counts + oldi, -1.0f);
            atomicAdd(g_counts + newi,  1.0f);
        }
        float2 q = *(const float2*)(emb + (size_t)newi * D + lane * 2);
        *(float2*)(out + OFF_Q + (size_t)row * D + lane * 2) = q;
        float2 xv = *(const float2*)(x + (size_t)row * D + lane * 2);
        atomicAdd(g_sum + (size_t)oldi * D + lane * 2,     -xv.x);
        atomicAdd(g_sum + (size_t)oldi * D + lane * 2 + 1, -xv.y);
        atomicAdd(g_sum + (size_t)newi * D + lane * 2,      xv.x);
        atomicAdd(g_sum + (size_t)newi * D + lane * 2 + 1,  xv.y);
    }
}

// ---------------------------------------------------------------------------
// k_final: EMA + laplace smoothing + renormalize.
// ---------------------------------------------------------------------------
__global__ __launch_bounds__(1024)
void k_final(const float* __restrict__ cs,
             const float* __restrict__ ea,
             float* __restrict__ out) {
    __shared__ float s_ncs[C_CODES];
    __shared__ float s_red[32];
    int tid = threadIdx.x;

    float local = 0.0f;
    for (int c = tid; c < C_CODES; c += 1024) {
        float v = cs[c] * DECAY_F + g_counts[c] * OMD_F;
        s_ncs[c] = v;
        out[OFF_NCS + c] = v;
        local += v;
    }
    #pragma unroll
    for (int m = 16; m >= 1; m >>= 1)
        local += __shfl_xor_sync(0xFFFFFFFFu, local, m);
    if ((tid & 31) == 0) s_red[tid >> 5] = local;
    __syncthreads();
    if (tid < 32) {
        float v = s_red[tid];
        #pragma unroll
        for (int m = 16; m >= 1; m >>= 1)
            v += __shfl_xor_sync(0xFFFFFFFFu, v, m);
        if (tid == 0) s_red[0] = v;
    }
    __syncthreads();
    float tot   = s_red[0];
    float denom = tot + (float)C_CODES * EPS_F;

    for (int i = tid; i < C_CODES * D; i += 1024) {
        int c = i >> 6;
        float nea = ea[i] * DECAY_F + g_sum[i] * OMD_F;
        out[OFF_NEA + i] = nea;
        float sm = (s_ncs[c] + EPS_F) / denom * tot;
        out[OFF_NE + i] = nea / sm;
    }
}

// ---------------------------------------------------------------------------
// kernel_launch
// ---------------------------------------------------------------------------
extern "C" void kernel_launch(void* const* d_in, const int* in_sizes, int n_in,
                              void* d_out, int out_size) {
    (void)in_sizes; (void)n_in; (void)out_size;
    const float* x   = (const float*)d_in[0];
    const float* emb = (const float*)d_in[1];
    const float* cs  = (const float*)d_in[2];
    const float* ea  = (const float*)d_in[3];
    float* out = (float*)d_out;

    cudaFuncSetAttribute(k_mma, cudaFuncAttributeMaxDynamicSharedMemorySize,
                         SMEM_DYN);
    cudaFuncSetAttribute(k_exact, cudaFuncAttributeMaxDynamicSharedMemorySize,
                         EX_SMEM);

    k_zero<<<512, 256>>>();
    k_prep_b<<<256, 256>>>(emb);
    k_mma<<<N_TOK / M_TILE, NTHR, SMEM_DYN>>>(x, emb, out);
    k_exact<<<1024, 256, EX_SMEM>>>(x, emb);
    k_fix<<<64, 256>>>(x, emb, out);
    k_final<<<1, 1024>>>(cs, ea, out);
}